// round 13
// baseline (speedup 1.0000x reference)
#include <cuda_runtime.h>
#include <cuda_bf16.h>
#include <math.h>
#include <stdint.h>

// Problem constants
#define Bc 4
#define Lc 1024
#define Dc 768
#define Hc 12
#define Mc 96
#define Ec 48
#define Pc 1024
#define BSc 64
#define NBc 12

// ---------------- scratch (single device global, no allocation) ----------------
constexpr long SZ_ENTITY  = (long)Bc * Ec * Dc;
constexpr long SZ_ENTATT  = (long)Bc * Hc * Ec * Lc;
constexpr long SZ_CTXATT  = (long)Bc * Pc * Lc;
constexpr long SZ_CTXT    = (long)Bc * Dc * Lc;
constexpr long SZ_BPD     = (long)Bc * Pc * Dc;
constexpr long SZ_W       = (long)Dc * Dc;

constexpr long O_ENTITY  = 0;
constexpr long O_ENTATT  = O_ENTITY + SZ_ENTITY;
constexpr long O_CTXATT  = O_ENTATT + SZ_ENTATT;     // tf32-rounded fp32
constexpr long O_CTXT    = O_CTXATT + SZ_CTXATT;     // tf32-rounded fp32 [B][D][L]
constexpr long O_CI      = O_CTXT + SZ_CTXT;         // tf32-rounded fp32
constexpr long O_EHHT    = O_CI + SZ_BPD;            // [256][1536]: entity@[Wh;Wt]^T
constexpr long O_BIAS    = O_EHHT + 256 * 1536;      // [1536]: bh+bhc | bt+btc
constexpr long O_WTF     = O_BIAS + 1536;            // 4 weights tf32 [N][K]: Whc,Wtc,Wh,Wt
constexpr long O_ETF     = O_WTF + 4 * SZ_W;         // entity tf32 padded [256][D]
constexpr long O_H2      = O_ETF + 256 * Dc;
constexpr long O_T2      = O_H2 + SZ_BPD;
constexpr long O_TOTAL   = O_T2 + SZ_BPD;

__device__ __align__(16) float g_buf[O_TOTAL];
__device__ int   g_nz_idx[(long)Bc * Ec * Lc];
__device__ float g_nz_w[(long)Bc * Ec * Lc];
__device__ int   g_nz_cnt[Bc * Ec];

__device__ __forceinline__ float f2tf(float f)
{
    unsigned r;
    asm("cvt.rna.tf32.f32 %0, %1;" : "=r"(r) : "f"(f));
    return __uint_as_float(r);
}

// ---------------- K2 (fused K1+K2): entity = log(em @ exp(mm @ context)), 0 if empty ----
__global__ void k_entity(const float* __restrict__ ctx, const float* __restrict__ em,
                         const float* __restrict__ mm)
{
    int be = blockIdx.x;
    int b  = be / Ec;
    __shared__ int   s_mc;
    __shared__ int   s_midx[Mc];
    __shared__ float s_mw[Mc];
    __shared__ int   s_lc;
    __shared__ int   s_lidx[Lc];
    __shared__ float s_lw[Lc];

    if (threadIdx.x < 32) {
        int cnt = 0;
        for (int base = 0; base < Mc; base += 32) {
            int m = base + threadIdx.x;
            float w = em[(long)be * Mc + m];
            unsigned msk = __ballot_sync(0xffffffffu, w != 0.f);
            if (w != 0.f) {
                int pos = cnt + __popc(msk & ((1u << threadIdx.x) - 1u));
                s_midx[pos] = m;
                s_mw[pos]   = w;
            }
            cnt += __popc(msk);
        }
        if (threadIdx.x == 0) s_mc = cnt;
    }
    __syncthreads();
    int mc = s_mc;

    float eacc[3] = {0.f, 0.f, 0.f};
    for (int j = 0; j < mc; j++) {
        if (threadIdx.x < 32) {
            const float* mrow = mm + ((long)b * Mc + s_midx[j]) * Lc;
            int cnt = 0;
            for (int base = 0; base < Lc; base += 32) {
                int l = base + threadIdx.x;
                float w = mrow[l];
                unsigned msk = __ballot_sync(0xffffffffu, w != 0.f);
                if (w != 0.f) {
                    int pos = cnt + __popc(msk & ((1u << threadIdx.x) - 1u));
                    s_lidx[pos] = l;
                    s_lw[pos]   = w;
                }
                cnt += __popc(msk);
            }
            if (threadIdx.x == 0) s_lc = cnt;
        }
        __syncthreads();
        int lc = s_lc;
        float wj = s_mw[j];
        #pragma unroll
        for (int q = 0; q < 3; q++) {
            int d = threadIdx.x + q * 256;
            float a = 0.f;
            for (int i = 0; i < lc; i++)
                a += s_lw[i] * ctx[((long)b * Lc + s_lidx[i]) * Dc + d];
            eacc[q] += wj * expf(a);
        }
        __syncthreads();
    }
    #pragma unroll
    for (int q = 0; q < 3; q++) {
        int d = threadIdx.x + q * 256;
        g_buf[O_ENTITY + (long)be * Dc + d] = (mc == 0) ? 0.f : logf(eacc[q]);
    }
}

// ---------------- K3: em_norm sparse rows ----------------
__global__ void k_emnorm(const float* __restrict__ em, const float* __restrict__ mm)
{
    int be = blockIdx.x;
    int b  = be / Ec;
    __shared__ int   s_mc;
    __shared__ int   s_midx[Mc];
    __shared__ float s_mw[Mc];
    __shared__ float s_tok[Lc];
    __shared__ float s_red[256];
    __shared__ float s_inv;

    if (threadIdx.x < 32) {
        int cnt = 0;
        for (int base = 0; base < Mc; base += 32) {
            int m = base + threadIdx.x;
            float w = em[(long)be * Mc + m];
            unsigned msk = __ballot_sync(0xffffffffu, w != 0.f);
            if (w != 0.f) {
                int pos = cnt + __popc(msk & ((1u << threadIdx.x) - 1u));
                s_midx[pos] = m;
                s_mw[pos]   = w;
            }
            cnt += __popc(msk);
        }
        if (threadIdx.x == 0) s_mc = cnt;
    }
    __syncthreads();
    int mc = s_mc;

    float part = 0.f;
    for (int l = threadIdx.x; l < Lc; l += 256) {
        float a = 0.f;
        for (int j = 0; j < mc; j++)
            a += s_mw[j] * mm[((long)b * Mc + s_midx[j]) * Lc + l];
        s_tok[l] = a;
        part += a;
    }
    s_red[threadIdx.x] = part;
    __syncthreads();
    for (int s = 128; s > 0; s >>= 1) {
        if (threadIdx.x < s) s_red[threadIdx.x] += s_red[threadIdx.x + s];
        __syncthreads();
    }
    if (threadIdx.x == 0) s_inv = 1.f / (s_red[0] + 1e-20f);
    __syncthreads();
    float inv = s_inv;

    if (threadIdx.x < 32) {
        int cnt = 0;
        for (int base = 0; base < Lc; base += 32) {
            int l = base + threadIdx.x;
            float v = s_tok[l];
            unsigned msk = __ballot_sync(0xffffffffu, v != 0.f);
            if (v != 0.f) {
                int pos = cnt + __popc(msk & ((1u << threadIdx.x) - 1u));
                g_nz_idx[(long)be * Lc + pos] = l;
                g_nz_w[(long)be * Lc + pos]   = v * inv;
            }
            cnt += __popc(msk);
        }
        if (threadIdx.x == 0) g_nz_cnt[be] = cnt;
    }
}

// ---------------- K4: ent_att gather (float4 vectorized) ----------------
__global__ void k_entatt(const float* __restrict__ att)
{
    int id = blockIdx.x;
    int e  = id % Ec;
    int bh = id / Ec;
    int b  = bh / Hc;
    int be = b * Ec + e;
    int cnt = g_nz_cnt[be];
    int tid = threadIdx.x;          // 256 threads x float4 = 1024 elems

    float4 acc = make_float4(0.f, 0.f, 0.f, 0.f);
    for (int j = 0; j < cnt; j++) {
        int   l = g_nz_idx[(long)be * Lc + j];
        float w = g_nz_w[(long)be * Lc + j];
        float4 rv = reinterpret_cast<const float4*>(att + ((long)bh * Lc + l) * Lc)[tid];
        acc.x += w * rv.x;
        acc.y += w * rv.y;
        acc.z += w * rv.z;
        acc.w += w * rv.w;
    }
    reinterpret_cast<float4*>(&g_buf[O_ENTATT + (long)id * Lc])[tid] = acc;
}

// ---------------- K5: ctx_att (normalized, pre-masked) -> tf32, float4 vectorized ------
__global__ void k_ctxatt(const int* __restrict__ hts)
{
    int bp = blockIdx.x;
    int b  = bp / Pc;
    int hi = hts[bp * 2];
    int ti = hts[bp * 2 + 1];
    float maskf = (hi + ti) != 0 ? 1.f : 0.f;
    int tid = threadIdx.x;          // 256 threads x float4 = 1024 elems

    const float4* ph = reinterpret_cast<const float4*>(
        &g_buf[O_ENTATT + ((long)b * Hc * Ec + hi) * Lc]);
    const float4* pt = reinterpret_cast<const float4*>(
        &g_buf[O_ENTATT + ((long)b * Hc * Ec + ti) * Lc]);
    const long step4 = (long)Ec * Lc / 4;

    float4 v = make_float4(0.f, 0.f, 0.f, 0.f);
    #pragma unroll
    for (int h = 0; h < Hc; h++) {
        float4 a = ph[h * step4 + tid];
        float4 c = pt[h * step4 + tid];
        v.x += a.x * c.x;
        v.y += a.y * c.y;
        v.z += a.z * c.z;
        v.w += a.w * c.w;
    }
    float part = (v.x + v.y) + (v.z + v.w);

    __shared__ float s_red[256];
    __shared__ float s_inv;
    s_red[tid] = part;
    __syncthreads();
    for (int s = 128; s > 0; s >>= 1) {
        if (tid < s) s_red[tid] += s_red[tid + s];
        __syncthreads();
    }
    if (tid == 0) s_inv = maskf / (s_red[0] + 1e-20f);
    __syncthreads();
    float inv = s_inv;
    float4 o;
    o.x = f2tf(v.x * inv);
    o.y = f2tf(v.y * inv);
    o.z = f2tf(v.z * inv);
    o.w = f2tf(v.w * inv);
    reinterpret_cast<float4*>(&g_buf[O_CTXATT + (long)bp * Lc])[tid] = o;
}

// ---------------- transpose context per batch: [L][D] -> [D][L] tf32 ----------------
__global__ void k_ctxT(const float* __restrict__ ctx)
{
    int b = blockIdx.z;
    const float* W = ctx + (long)b * Lc * Dc;
    float* O = &g_buf[O_CTXT + (long)b * Dc * Lc];
    __shared__ float t[32][33];
    int x  = blockIdx.x * 32 + threadIdx.x;   // d
    int y0 = blockIdx.y * 32;                 // l
    for (int i = threadIdx.y; i < 32; i += 8)
        t[i][threadIdx.x] = W[(long)(y0 + i) * Dc + x];
    __syncthreads();
    int x2 = blockIdx.y * 32 + threadIdx.x;   // l
    for (int i = threadIdx.y; i < 32; i += 8)
        O[(long)(blockIdx.x * 32 + i) * Lc + x2] = f2tf(t[threadIdx.x][i]);
}

// ---------------- convert 4 weight matrices fp32 [N][K] -> tf32 raw ----------------
__global__ void k_w2tf(const float* __restrict__ W0, const float* __restrict__ W1,
                       const float* __restrict__ W2, const float* __restrict__ W3)
{
    const float* W = (blockIdx.y == 0) ? W0 : (blockIdx.y == 1) ? W1 : (blockIdx.y == 2) ? W2 : W3;
    float* D = &g_buf[O_WTF + (long)blockIdx.y * SZ_W];
    long i = ((long)blockIdx.x * 256 + threadIdx.x) * 4;
    float4 v = *reinterpret_cast<const float4*>(&W[i]);
    v.x = f2tf(v.x); v.y = f2tf(v.y); v.z = f2tf(v.z); v.w = f2tf(v.w);
    *reinterpret_cast<float4*>(&D[i]) = v;
}

// ---------------- entity fp32 [192][D] -> tf32 [256][D] (zero pad); bias2; out init ----------------
__global__ void k_ent2tf(const float* __restrict__ bh, const float* __restrict__ bhc,
                         const float* __restrict__ bt, const float* __restrict__ btc,
                         const float* __restrict__ bbin, float* __restrict__ out)
{
    long i = ((long)blockIdx.x * 256 + threadIdx.x) * 4;   // over 256*768
    int row = (int)(i / Dc);
    float4 v = make_float4(0.f, 0.f, 0.f, 0.f);
    if (row < Bc * Ec) {
        v = *reinterpret_cast<const float4*>(&g_buf[O_ENTITY + i]);
        v.x = f2tf(v.x); v.y = f2tf(v.y); v.z = f2tf(v.z); v.w = f2tf(v.w);
    }
    *reinterpret_cast<float4*>(&g_buf[O_ETF + i]) = v;
    int t = blockIdx.x * 256 + threadIdx.x;
    if (t < 768)        g_buf[O_BIAS + t] = bh[t] + bhc[t];
    else if (t < 1536)  g_buf[O_BIAS + t] = bt[t - 768] + btc[t - 768];
    if (t < Bc * Pc * 2) out[t] = bbin[t & 1];
}

// ================= tf32 mma.sync GEMM: C[m][n] = sum_k A[m][k] * B[n][k] =================
// 128x128 block tile, 256 threads (proven R9 config), K-tile 32, cp.async double-buffered,
// rows padded to 144B. MODE 0: fp32 out. MODE 1: tf32-rounded out. MODE 2: fused act epilogue.
__device__ __forceinline__ uint32_t smem_u32(const void* p)
{
    uint32_t a;
    asm("{ .reg .u64 t; cvta.to.shared.u64 t, %1; cvt.u32.u64 %0, t; }" : "=r"(a) : "l"(p));
    return a;
}

#define TC_ROWB   144
#define TC_STAGE  (128 * TC_ROWB)
#define TC_SMEM   (4 * TC_STAGE)

template <int MODE>
__global__ __launch_bounds__(256) void tc_gemm(
    const float* __restrict__ A, const float* __restrict__ B, float* __restrict__ C,
    int M, int N, int K, long sA, long sB, long sC, const int* __restrict__ hts)
{
    extern __shared__ __align__(16) char smem[];
    A += (long)blockIdx.z * sA;
    B += (long)blockIdx.z * sB;
    C += (long)blockIdx.z * sC;

    const uint32_t sb = smem_u32(smem);
    const int tid  = threadIdx.x;
    const int lane = tid & 31;
    const int wid  = tid >> 5;
    const int g    = lane >> 2;
    const int tig  = lane & 3;
    const int mwo  = (wid >> 2) * 64;
    const int nwo  = (wid & 3) * 32;
    const int m0   = blockIdx.y * 128;
    const int n0   = blockIdx.x * 128;

    const int crow = tid >> 1;
    const int cseg = (tid & 1) * 4;

    float acc[4][4][4];
    #pragma unroll
    for (int mt = 0; mt < 4; mt++)
        #pragma unroll
        for (int nt = 0; nt < 4; nt++)
            #pragma unroll
            for (int q = 0; q < 4; q++) acc[mt][nt][q] = 0.f;

    const int nch = K >> 5;

    auto issue = [&](int c) {
        int s = c & 1;
        int k0 = c << 5;
        uint32_t da = sb + s * (2 * TC_STAGE) + crow * TC_ROWB;
        const float* pa = A + (long)(m0 + crow) * K + k0;
        #pragma unroll
        for (int j = 0; j < 4; j++)
            asm volatile("cp.async.cg.shared.global [%0], [%1], 16;"
                         :: "r"(da + (cseg + j) * 16), "l"(pa + (cseg + j) * 4));
        uint32_t db = da + TC_STAGE;
        const float* pb = B + (long)(n0 + crow) * K + k0;
        #pragma unroll
        for (int j = 0; j < 4; j++)
            asm volatile("cp.async.cg.shared.global [%0], [%1], 16;"
                         :: "r"(db + (cseg + j) * 16), "l"(pb + (cseg + j) * 4));
        asm volatile("cp.async.commit_group;" ::: "memory");
    };

    issue(0);
    for (int c = 0; c < nch; c++) {
        if (c + 1 < nch) {
            issue(c + 1);
            asm volatile("cp.async.wait_group 1;" ::: "memory");
        } else {
            asm volatile("cp.async.wait_group 0;" ::: "memory");
        }
        __syncthreads();

        const uint32_t* Aw = reinterpret_cast<const uint32_t*>(smem + (c & 1) * 2 * TC_STAGE);
        const uint32_t* Bw = reinterpret_cast<const uint32_t*>(smem + (c & 1) * 2 * TC_STAGE + TC_STAGE);

        #pragma unroll
        for (int ks = 0; ks < 4; ks++) {
            const int kw = ks * 8 + tig;
            uint32_t af[4][4], bfr[4][2];
            #pragma unroll
            for (int mt = 0; mt < 4; mt++) {
                int r = mwo + mt * 16 + g;
                af[mt][0] = Aw[r * 36 + kw];
                af[mt][1] = Aw[(r + 8) * 36 + kw];
                af[mt][2] = Aw[r * 36 + kw + 4];
                af[mt][3] = Aw[(r + 8) * 36 + kw + 4];
            }
            #pragma unroll
            for (int nt = 0; nt < 4; nt++) {
                int cc = nwo + nt * 8 + g;
                bfr[nt][0] = Bw[cc * 36 + kw];
                bfr[nt][1] = Bw[cc * 36 + kw + 4];
            }
            #pragma unroll
            for (int mt = 0; mt < 4; mt++)
                #pragma unroll
                for (int nt = 0; nt < 4; nt++) {
                    asm volatile(
                        "mma.sync.aligned.m16n8k8.row.col.f32.tf32.tf32.f32 "
                        "{%0,%1,%2,%3}, {%4,%5,%6,%7}, {%8,%9}, {%0,%1,%2,%3};\n"
                        : "+f"(acc[mt][nt][0]), "+f"(acc[mt][nt][1]),
                          "+f"(acc[mt][nt][2]), "+f"(acc[mt][nt][3])
                        : "r"(af[mt][0]), "r"(af[mt][1]), "r"(af[mt][2]), "r"(af[mt][3]),
                          "r"(bfr[nt][0]), "r"(bfr[nt][1]));
                }
        }
        __syncthreads();
    }

    if (MODE == 2) {
        // fused activation epilogue: this 128-col block is entirely h (n0<768) or t side
        const bool isT = (n0 >= 768);
        const long dstBase = isT ? O_T2 : O_H2;
        const int  colOff  = isT ? 768 : 0;
        #pragma unroll
        for (int mt = 0; mt < 4; mt++) {
            #pragma unroll
            for (int half = 0; half < 2; half++) {
                int row = m0 + mwo + mt * 16 + g + half * 8;
                int b   = row >> 10;
                int hi  = hts[row * 2];
                int ti  = hts[row * 2 + 1];
                float maskf = (hi + ti) != 0 ? 1.f : 0.f;
                long erow = (long)(b * Ec + (isT ? ti : hi)) * 1536;
                #pragma unroll
                for (int nt = 0; nt < 4; nt++) {
                    int col = n0 + nwo + nt * 8 + tig * 2;
                    float2 e  = *reinterpret_cast<const float2*>(&g_buf[O_EHHT + erow + col]);
                    float2 bb = *reinterpret_cast<const float2*>(&g_buf[O_BIAS + col]);
                    float v0 = tanhf(acc[mt][nt][half * 2 + 0] + maskf * e.x + bb.x);
                    float v1 = tanhf(acc[mt][nt][half * 2 + 1] + maskf * e.y + bb.y);
                    *reinterpret_cast<float2*>(
                        &g_buf[dstBase + (long)row * Dc + col - colOff]) = make_float2(v0, v1);
                }
            }
        }
    } else {
        #pragma unroll
        for (int mt = 0; mt < 4; mt++) {
            int row = m0 + mwo + mt * 16 + g;
            #pragma unroll
            for (int nt = 0; nt < 4; nt++) {
                int col = n0 + nwo + nt * 8 + tig * 2;
                float2 v0 = make_float2(acc[mt][nt][0], acc[mt][nt][1]);
                float2 v1 = make_float2(acc[mt][nt][2], acc[mt][nt][3]);
                if (MODE == 1) {
                    v0.x = f2tf(v0.x); v0.y = f2tf(v0.y);
                    v1.x = f2tf(v1.x); v1.y = f2tf(v1.y);
                }
                *reinterpret_cast<float2*>(&C[(long)row * N + col])       = v0;
                *reinterpret_cast<float2*>(&C[(long)(row + 8) * N + col]) = v1;
            }
        }
    }
}

// ---------------- K9 fused (R9 form): bin_res += h2-tile · (t2-tile @ Wb^T) ----------------
__global__ __launch_bounds__(256) void k_binred(const float* __restrict__ Wbin,
                                                float* __restrict__ out)
{
    int mt = blockIdx.x;            // 64-row tile (0..63)
    int n  = blockIdx.y;            // 0..11
    int o  = blockIdx.z;            // 0..1
    __shared__ float sA[64][65];    // t2 tile
    __shared__ float sW[64][65];    // W transposed: sW[j][i]
    int tid = threadIdx.x;

    #pragma unroll
    for (int q = 0; q < 4; q++) {
        int idx = tid + q * 256;
        int r   = idx >> 4;
        int c4  = idx & 15;
        float4 v = *reinterpret_cast<const float4*>(
            &g_buf[O_T2 + (long)(mt * 64 + r) * Dc + n * 64 + c4 * 4]);
        sA[r][c4 * 4 + 0] = v.x;
        sA[r][c4 * 4 + 1] = v.y;
        sA[r][c4 * 4 + 2] = v.z;
        sA[r][c4 * 4 + 3] = v.w;
        float4 w = *reinterpret_cast<const float4*>(
            &Wbin[(long)o * (Dc * BSc) + n * 4096 + r * 64 + c4 * 4]);
        sW[c4 * 4 + 0][r] = w.x;
        sW[c4 * 4 + 1][r] = w.y;
        sW[c4 * 4 + 2][r] = w.z;
        sW[c4 * 4 + 3][r] = w.w;
    }
    __syncthreads();

    int tx = tid & 15, ty = tid >> 4;
    float acc[4][4];
    #pragma unroll
    for (int i = 0; i < 4; i++)
        #pragma unroll
        for (int j = 0; j < 4; j++) acc[i][j] = 0.f;

    #pragma unroll 8
    for (int k = 0; k < 64; k++) {
        float ar[4], br[4];
        #pragma unroll
        for (int r = 0; r < 4; r++) ar[r] = sA[ty * 4 + r][k];
        #pragma unroll
        for (int c = 0; c < 4; c++) br[c] = sW[k][tx * 4 + c];
        #pragma unroll
        for (int r = 0; r < 4; r++)
            #pragma unroll
            for (int c = 0; c < 4; c++)
                acc[r][c] = fmaf(ar[r], br[c], acc[r][c]);
    }

    float part[4];
    #pragma unroll
    for (int r = 0; r < 4; r++) {
        float4 h = *reinterpret_cast<const float4*>(
            &g_buf[O_H2 + (long)(mt * 64 + ty * 4 + r) * Dc + n * 64 + tx * 4]);
        float p;
        p = fmaf(acc[r][0], h.x, 0.f);
        p = fmaf(acc[r][1], h.y, p);
        p = fmaf(acc[r][2], h.z, p);
        p = fmaf(acc[r][3], h.w, p);
        part[r] = p;
    }
    #pragma unroll
    for (int m = 8; m > 0; m >>= 1) {
        #pragma unroll
        for (int r = 0; r < 4; r++)
            part[r] += __shfl_xor_sync(0xffffffffu, part[r], m);
    }
    if (tx == 0) {
        #pragma unroll
        for (int r = 0; r < 4; r++)
            atomicAdd(&out[(mt * 64 + ty * 4 + r) * 2 + o], part[r]);
    }
}

// ---------------- host launch ----------------
extern "C" void kernel_launch(void* const* d_in, const int* in_sizes, int n_in,
                              void* d_out, int out_size)
{
    const float* ctx  = (const float*)d_in[0];
    const float* att  = (const float*)d_in[1];
    const float* mm   = (const float*)d_in[2];
    const float* em   = (const float*)d_in[3];
    const int*   hts  = (const int*)d_in[4];
    const float* Wh   = (const float*)d_in[5];
    const float* bh   = (const float*)d_in[6];
    const float* Whc  = (const float*)d_in[7];
    const float* bhc  = (const float*)d_in[8];
    const float* Wt   = (const float*)d_in[9];
    const float* bt   = (const float*)d_in[10];
    const float* Wtc  = (const float*)d_in[11];
    const float* btc  = (const float*)d_in[12];
    const float* Wbin = (const float*)d_in[13];
    const float* bbin = (const float*)d_in[14];
    float* out = (float*)d_out;

    float* buf = nullptr;
    cudaGetSymbolAddress((void**)&buf, g_buf);

    cudaFuncSetAttribute(tc_gemm<0>, cudaFuncAttributeMaxDynamicSharedMemorySize, TC_SMEM);
    cudaFuncSetAttribute(tc_gemm<1>, cudaFuncAttributeMaxDynamicSharedMemorySize, TC_SMEM);
    cudaFuncSetAttribute(tc_gemm<2>, cudaFuncAttributeMaxDynamicSharedMemorySize, TC_SMEM);

    // stage 1: sparse pooling (mention fused into entity) + operand conversion
    k_ctxT<<<dim3(Dc / 32, Lc / 32, Bc), dim3(32, 8)>>>(ctx);
    k_w2tf<<<dim3((int)(SZ_W / 1024), 4), 256>>>(Whc, Wtc, Wh, Wt);
    k_entity<<<Bc * Ec, 256>>>(ctx, em, mm);
    k_emnorm<<<Bc * Ec, 256>>>(em, mm);
    k_ent2tf<<<(256 * Dc) / 1024, 256>>>(bh, bhc, bt, btc, bbin, out);

    // stage 2: entity attention (float4 vectorized)
    k_entatt<<<Bc * Hc * Ec, 256>>>(att);
    k_ctxatt<<<Bc * Pc, 256>>>(hts);

    // stage 3: GEMMs (tf32 mma.sync, 128x128 tiles — proven R9 config)
    // entity @ [Wh;Wt]^T -> EHHT
    tc_gemm<0><<<dim3(1536 / 128, 2, 1), 256, TC_SMEM>>>(
        buf + O_ETF, buf + O_WTF + 2 * SZ_W, buf + O_EHHT, 256, 1536, Dc, 0, 0, 0, nullptr);

    // ci[b] = ctx_att[b] (P x L) @ context[b]  -> tf32-rounded out
    tc_gemm<1><<<dim3(Dc / 128, Pc / 128, Bc), 256, TC_SMEM>>>(
        buf + O_CTXATT, buf + O_CTXT, buf + O_CI,
        Pc, Dc, Lc, (long)Pc * Lc, (long)Dc * Lc, (long)Pc * Dc, nullptr);

    // ci @ [Whc;Wtc]^T with fused activation epilogue -> H2 / T2 directly
    tc_gemm<2><<<dim3(1536 / 128, (Bc * Pc) / 128, 1), 256, TC_SMEM>>>(
        buf + O_CI, buf + O_WTF, nullptr, Bc * Pc, 1536, Dc, 0, 0, 0, hts);

    // stage 4: fused grouped bilinear (R9 grid — 1536 blocks)
    k_binred<<<dim3((Bc * Pc) / 64, NBc, 2), 256>>>(Wbin, out);
}

// round 14
// speedup vs baseline: 1.0653x; 1.0653x over previous
#include <cuda_runtime.h>
#include <cuda_bf16.h>
#include <math.h>
#include <stdint.h>

// Problem constants
#define Bc 4
#define Lc 1024
#define Dc 768
#define Hc 12
#define Mc 96
#define Ec 48
#define Pc 1024
#define BSc 64
#define NBc 12

// ---------------- scratch (single device global, no allocation) ----------------
constexpr long SZ_ENTITY  = (long)Bc * Ec * Dc;
constexpr long SZ_ENTATT  = (long)Bc * Hc * Ec * Lc;
constexpr long SZ_CTXATT  = (long)Bc * Pc * Lc;
constexpr long SZ_CTXT    = (long)Bc * Dc * Lc;
constexpr long SZ_BPD     = (long)Bc * Pc * Dc;
constexpr long SZ_W       = (long)Dc * Dc;

constexpr long O_ENTITY  = 0;
constexpr long O_ENTATT  = O_ENTITY + SZ_ENTITY;
constexpr long O_CTXATT  = O_ENTATT + SZ_ENTATT;     // tf32-rounded fp32
constexpr long O_CTXT    = O_CTXATT + SZ_CTXATT;     // tf32-rounded fp32 [B][D][L]
constexpr long O_CI      = O_CTXT + SZ_CTXT;         // tf32-rounded fp32
constexpr long O_EHHT    = O_CI + SZ_BPD;            // [256][1536]: entity@[Wh;Wt]^T
constexpr long O_BIAS    = O_EHHT + 256 * 1536;      // [1536]: bh+bhc | bt+btc
constexpr long O_WTF     = O_BIAS + 1536;            // 4 weights tf32 [N][K]: Whc,Wtc,Wh,Wt
constexpr long O_ETF     = O_WTF + 4 * SZ_W;         // entity tf32 padded [256][D]
constexpr long O_H2      = O_ETF + 256 * Dc;
constexpr long O_T2      = O_H2 + SZ_BPD;
constexpr long O_TOTAL   = O_T2 + SZ_BPD;

__device__ __align__(16) float g_buf[O_TOTAL];
__device__ int   g_nz_idx[(long)Bc * Ec * Lc];
__device__ float g_nz_w[(long)Bc * Ec * Lc];
__device__ int   g_nz_cnt[Bc * Ec];

__device__ __forceinline__ float f2tf(float f)
{
    unsigned r;
    asm("cvt.rna.tf32.f32 %0, %1;" : "=r"(r) : "f"(f));
    return __uint_as_float(r);
}

// ---------------- shared-memory union for the fused prep1 kernel ----------------
struct SEnt  { int mc; int midx[Mc]; float mw[Mc]; int lc; int lidx[Lc]; float lw[Lc]; };
struct SNorm { int mc; int midx[Mc]; float mw[Mc]; float tok[Lc]; float red[256]; float inv; };
struct SCtxT { float t[32][33]; };

// grid layout for prep1 (all bodies 256 threads, mutually independent):
//   [0, 192)              entity  (fused mention+entity)
//   [192, 384)            emnorm
//   [384, 384+2304)       w2tf    (4 matrices x 576 blocks)
//   [2688, 2688+3072)     ctxT    (24 x 32 x 4)
#define P1_ENTITY_END  192
#define P1_EMNORM_END  384
#define P1_W2TF_END    (384 + 2304)
#define P1_TOTAL       (2688 + 3072)

__device__ void body_entity(void* smem, int be,
                            const float* __restrict__ ctx, const float* __restrict__ em,
                            const float* __restrict__ mm)
{
    SEnt* s = reinterpret_cast<SEnt*>(smem);
    int b = be / Ec;

    if (threadIdx.x < 32) {
        int cnt = 0;
        for (int base = 0; base < Mc; base += 32) {
            int m = base + threadIdx.x;
            float w = em[(long)be * Mc + m];
            unsigned msk = __ballot_sync(0xffffffffu, w != 0.f);
            if (w != 0.f) {
                int pos = cnt + __popc(msk & ((1u << threadIdx.x) - 1u));
                s->midx[pos] = m;
                s->mw[pos]   = w;
            }
            cnt += __popc(msk);
        }
        if (threadIdx.x == 0) s->mc = cnt;
    }
    __syncthreads();
    int mc = s->mc;

    float eacc[3] = {0.f, 0.f, 0.f};
    for (int j = 0; j < mc; j++) {
        if (threadIdx.x < 32) {
            const float* mrow = mm + ((long)b * Mc + s->midx[j]) * Lc;
            int cnt = 0;
            for (int base = 0; base < Lc; base += 32) {
                int l = base + threadIdx.x;
                float w = mrow[l];
                unsigned msk = __ballot_sync(0xffffffffu, w != 0.f);
                if (w != 0.f) {
                    int pos = cnt + __popc(msk & ((1u << threadIdx.x) - 1u));
                    s->lidx[pos] = l;
                    s->lw[pos]   = w;
                }
                cnt += __popc(msk);
            }
            if (threadIdx.x == 0) s->lc = cnt;
        }
        __syncthreads();
        int lc = s->lc;
        float wj = s->mw[j];
        #pragma unroll
        for (int q = 0; q < 3; q++) {
            int d = threadIdx.x + q * 256;
            float a = 0.f;
            for (int i = 0; i < lc; i++)
                a += s->lw[i] * ctx[((long)b * Lc + s->lidx[i]) * Dc + d];
            eacc[q] += wj * expf(a);
        }
        __syncthreads();
    }
    #pragma unroll
    for (int q = 0; q < 3; q++) {
        int d = threadIdx.x + q * 256;
        g_buf[O_ENTITY + (long)be * Dc + d] = (mc == 0) ? 0.f : logf(eacc[q]);
    }
}

__device__ void body_emnorm(void* smem, int be,
                            const float* __restrict__ em, const float* __restrict__ mm)
{
    SNorm* s = reinterpret_cast<SNorm*>(smem);
    int b = be / Ec;

    if (threadIdx.x < 32) {
        int cnt = 0;
        for (int base = 0; base < Mc; base += 32) {
            int m = base + threadIdx.x;
            float w = em[(long)be * Mc + m];
            unsigned msk = __ballot_sync(0xffffffffu, w != 0.f);
            if (w != 0.f) {
                int pos = cnt + __popc(msk & ((1u << threadIdx.x) - 1u));
                s->midx[pos] = m;
                s->mw[pos]   = w;
            }
            cnt += __popc(msk);
        }
        if (threadIdx.x == 0) s->mc = cnt;
    }
    __syncthreads();
    int mc = s->mc;

    float part = 0.f;
    for (int l = threadIdx.x; l < Lc; l += 256) {
        float a = 0.f;
        for (int j = 0; j < mc; j++)
            a += s->mw[j] * mm[((long)b * Mc + s->midx[j]) * Lc + l];
        s->tok[l] = a;
        part += a;
    }
    s->red[threadIdx.x] = part;
    __syncthreads();
    for (int st = 128; st > 0; st >>= 1) {
        if (threadIdx.x < st) s->red[threadIdx.x] += s->red[threadIdx.x + st];
        __syncthreads();
    }
    if (threadIdx.x == 0) s->inv = 1.f / (s->red[0] + 1e-20f);
    __syncthreads();
    float inv = s->inv;

    if (threadIdx.x < 32) {
        int cnt = 0;
        for (int base = 0; base < Lc; base += 32) {
            int l = base + threadIdx.x;
            float v = s->tok[l];
            unsigned msk = __ballot_sync(0xffffffffu, v != 0.f);
            if (v != 0.f) {
                int pos = cnt + __popc(msk & ((1u << threadIdx.x) - 1u));
                g_nz_idx[(long)be * Lc + pos] = l;
                g_nz_w[(long)be * Lc + pos]   = v * inv;
            }
            cnt += __popc(msk);
        }
        if (threadIdx.x == 0) g_nz_cnt[be] = cnt;
    }
}

__device__ void body_w2tf(int blk, const float* __restrict__ W0, const float* __restrict__ W1,
                          const float* __restrict__ W2, const float* __restrict__ W3)
{
    int wsel = blk / 576;
    int bx   = blk % 576;
    const float* W = (wsel == 0) ? W0 : (wsel == 1) ? W1 : (wsel == 2) ? W2 : W3;
    float* D = &g_buf[O_WTF + (long)wsel * SZ_W];
    long i = ((long)bx * 256 + threadIdx.x) * 4;
    float4 v = *reinterpret_cast<const float4*>(&W[i]);
    v.x = f2tf(v.x); v.y = f2tf(v.y); v.z = f2tf(v.z); v.w = f2tf(v.w);
    *reinterpret_cast<float4*>(&D[i]) = v;
}

__device__ void body_ctxT(void* smem, int blk, const float* __restrict__ ctx)
{
    SCtxT* s = reinterpret_cast<SCtxT*>(smem);
    int bx = blk % 24;             // d tile
    int by = (blk / 24) % 32;      // l tile
    int b  = blk / (24 * 32);
    int tx = threadIdx.x & 31;
    int ty = threadIdx.x >> 5;     // 0..7
    const float* W = ctx + (long)b * Lc * Dc;
    float* O = &g_buf[O_CTXT + (long)b * Dc * Lc];
    int x  = bx * 32 + tx;
    int y0 = by * 32;
    for (int i = ty; i < 32; i += 8)
        s->t[i][tx] = W[(long)(y0 + i) * Dc + x];
    __syncthreads();
    int x2 = by * 32 + tx;
    for (int i = ty; i < 32; i += 8)
        O[(long)(bx * 32 + i) * Lc + x2] = f2tf(s->t[tx][i]);
}

// ---------------- prep1: entity | emnorm | w2tf | ctxT (independent, fused) ----------------
__global__ __launch_bounds__(256) void k_prep1(
    const float* __restrict__ ctx, const float* __restrict__ em, const float* __restrict__ mm,
    const float* __restrict__ W0, const float* __restrict__ W1,
    const float* __restrict__ W2, const float* __restrict__ W3)
{
    __shared__ __align__(16) char pool[sizeof(SEnt)];
    int blk = blockIdx.x;
    if (blk < P1_ENTITY_END) {
        body_entity(pool, blk, ctx, em, mm);
    } else if (blk < P1_EMNORM_END) {
        body_emnorm(pool, blk - P1_ENTITY_END, em, mm);
    } else if (blk < P1_W2TF_END) {
        body_w2tf(blk - P1_EMNORM_END, W0, W1, W2, W3);
    } else {
        body_ctxT(pool, blk - P1_W2TF_END, ctx);
    }
}

// ---------------- prep2: ent2tf+bias+outinit | entatt (independent, fused) ----------------
// grid: [0,192) ent2tf ; [192, 192+2304) entatt
#define P2_ENT2TF_END 192
#define P2_TOTAL      (192 + 2304)

__device__ void body_ent2tf(int blk,
                            const float* __restrict__ bh, const float* __restrict__ bhc,
                            const float* __restrict__ bt, const float* __restrict__ btc,
                            const float* __restrict__ bbin, float* __restrict__ out)
{
    long i = ((long)blk * 256 + threadIdx.x) * 4;   // over 256*768
    int row = (int)(i / Dc);
    float4 v = make_float4(0.f, 0.f, 0.f, 0.f);
    if (row < Bc * Ec) {
        v = *reinterpret_cast<const float4*>(&g_buf[O_ENTITY + i]);
        v.x = f2tf(v.x); v.y = f2tf(v.y); v.z = f2tf(v.z); v.w = f2tf(v.w);
    }
    *reinterpret_cast<float4*>(&g_buf[O_ETF + i]) = v;
    int t = blk * 256 + threadIdx.x;
    if (t < 768)        g_buf[O_BIAS + t] = bh[t] + bhc[t];
    else if (t < 1536)  g_buf[O_BIAS + t] = bt[t - 768] + btc[t - 768];
    if (t < Bc * Pc * 2) out[t] = bbin[t & 1];
}

__device__ void body_entatt(int id, const float* __restrict__ att)
{
    int e  = id % Ec;
    int bh = id / Ec;
    int b  = bh / Hc;
    int be = b * Ec + e;
    int cnt = g_nz_cnt[be];
    int tid = threadIdx.x;

    float4 acc = make_float4(0.f, 0.f, 0.f, 0.f);
    for (int j = 0; j < cnt; j++) {
        int   l = g_nz_idx[(long)be * Lc + j];
        float w = g_nz_w[(long)be * Lc + j];
        float4 rv = reinterpret_cast<const float4*>(att + ((long)bh * Lc + l) * Lc)[tid];
        acc.x += w * rv.x;
        acc.y += w * rv.y;
        acc.z += w * rv.z;
        acc.w += w * rv.w;
    }
    reinterpret_cast<float4*>(&g_buf[O_ENTATT + (long)id * Lc])[tid] = acc;
}

__global__ __launch_bounds__(256) void k_prep2(
    const float* __restrict__ att,
    const float* __restrict__ bh, const float* __restrict__ bhc,
    const float* __restrict__ bt, const float* __restrict__ btc,
    const float* __restrict__ bbin, float* __restrict__ out)
{
    int blk = blockIdx.x;
    if (blk < P2_ENT2TF_END)
        body_ent2tf(blk, bh, bhc, bt, btc, bbin, out);
    else
        body_entatt(blk - P2_ENT2TF_END, att);
}

// ---------------- K5: ctx_att (normalized, pre-masked) -> tf32, float4 ----------------
__global__ void k_ctxatt(const int* __restrict__ hts)
{
    int bp = blockIdx.x;
    int b  = bp / Pc;
    int hi = hts[bp * 2];
    int ti = hts[bp * 2 + 1];
    float maskf = (hi + ti) != 0 ? 1.f : 0.f;
    int tid = threadIdx.x;

    const float4* ph = reinterpret_cast<const float4*>(
        &g_buf[O_ENTATT + ((long)b * Hc * Ec + hi) * Lc]);
    const float4* pt = reinterpret_cast<const float4*>(
        &g_buf[O_ENTATT + ((long)b * Hc * Ec + ti) * Lc]);
    const long step4 = (long)Ec * Lc / 4;

    float4 v = make_float4(0.f, 0.f, 0.f, 0.f);
    #pragma unroll
    for (int h = 0; h < Hc; h++) {
        float4 a = ph[h * step4 + tid];
        float4 c = pt[h * step4 + tid];
        v.x += a.x * c.x;
        v.y += a.y * c.y;
        v.z += a.z * c.z;
        v.w += a.w * c.w;
    }
    float part = (v.x + v.y) + (v.z + v.w);

    __shared__ float s_red[256];
    __shared__ float s_inv;
    s_red[tid] = part;
    __syncthreads();
    for (int s = 128; s > 0; s >>= 1) {
        if (tid < s) s_red[tid] += s_red[tid + s];
        __syncthreads();
    }
    if (tid == 0) s_inv = maskf / (s_red[0] + 1e-20f);
    __syncthreads();
    float inv = s_inv;
    float4 o;
    o.x = f2tf(v.x * inv);
    o.y = f2tf(v.y * inv);
    o.z = f2tf(v.z * inv);
    o.w = f2tf(v.w * inv);
    reinterpret_cast<float4*>(&g_buf[O_CTXATT + (long)bp * Lc])[tid] = o;
}

// ================= tf32 mma.sync GEMM (proven R9 config) =================
__device__ __forceinline__ uint32_t smem_u32(const void* p)
{
    uint32_t a;
    asm("{ .reg .u64 t; cvta.to.shared.u64 t, %1; cvt.u32.u64 %0, t; }" : "=r"(a) : "l"(p));
    return a;
}

#define TC_ROWB   144
#define TC_STAGE  (128 * TC_ROWB)
#define TC_SMEM   (4 * TC_STAGE)

template <int MODE>
__global__ __launch_bounds__(256) void tc_gemm(
    const float* __restrict__ A, const float* __restrict__ B, float* __restrict__ C,
    int M, int N, int K, long sA, long sB, long sC, const int* __restrict__ hts)
{
    extern __shared__ __align__(16) char smem[];
    A += (long)blockIdx.z * sA;
    B += (long)blockIdx.z * sB;
    C += (long)blockIdx.z * sC;

    const uint32_t sb = smem_u32(smem);
    const int tid  = threadIdx.x;
    const int lane = tid & 31;
    const int wid  = tid >> 5;
    const int g    = lane >> 2;
    const int tig  = lane & 3;
    const int mwo  = (wid >> 2) * 64;
    const int nwo  = (wid & 3) * 32;
    const int m0   = blockIdx.y * 128;
    const int n0   = blockIdx.x * 128;

    const int crow = tid >> 1;
    const int cseg = (tid & 1) * 4;

    float acc[4][4][4];
    #pragma unroll
    for (int mt = 0; mt < 4; mt++)
        #pragma unroll
        for (int nt = 0; nt < 4; nt++)
            #pragma unroll
            for (int q = 0; q < 4; q++) acc[mt][nt][q] = 0.f;

    const int nch = K >> 5;

    auto issue = [&](int c) {
        int s = c & 1;
        int k0 = c << 5;
        uint32_t da = sb + s * (2 * TC_STAGE) + crow * TC_ROWB;
        const float* pa = A + (long)(m0 + crow) * K + k0;
        #pragma unroll
        for (int j = 0; j < 4; j++)
            asm volatile("cp.async.cg.shared.global [%0], [%1], 16;"
                         :: "r"(da + (cseg + j) * 16), "l"(pa + (cseg + j) * 4));
        uint32_t db = da + TC_STAGE;
        const float* pb = B + (long)(n0 + crow) * K + k0;
        #pragma unroll
        for (int j = 0; j < 4; j++)
            asm volatile("cp.async.cg.shared.global [%0], [%1], 16;"
                         :: "r"(db + (cseg + j) * 16), "l"(pb + (cseg + j) * 4));
        asm volatile("cp.async.commit_group;" ::: "memory");
    };

    issue(0);
    for (int c = 0; c < nch; c++) {
        if (c + 1 < nch) {
            issue(c + 1);
            asm volatile("cp.async.wait_group 1;" ::: "memory");
        } else {
            asm volatile("cp.async.wait_group 0;" ::: "memory");
        }
        __syncthreads();

        const uint32_t* Aw = reinterpret_cast<const uint32_t*>(smem + (c & 1) * 2 * TC_STAGE);
        const uint32_t* Bw = reinterpret_cast<const uint32_t*>(smem + (c & 1) * 2 * TC_STAGE + TC_STAGE);

        #pragma unroll
        for (int ks = 0; ks < 4; ks++) {
            const int kw = ks * 8 + tig;
            uint32_t af[4][4], bfr[4][2];
            #pragma unroll
            for (int mt = 0; mt < 4; mt++) {
                int r = mwo + mt * 16 + g;
                af[mt][0] = Aw[r * 36 + kw];
                af[mt][1] = Aw[(r + 8) * 36 + kw];
                af[mt][2] = Aw[r * 36 + kw + 4];
                af[mt][3] = Aw[(r + 8) * 36 + kw + 4];
            }
            #pragma unroll
            for (int nt = 0; nt < 4; nt++) {
                int cc = nwo + nt * 8 + g;
                bfr[nt][0] = Bw[cc * 36 + kw];
                bfr[nt][1] = Bw[cc * 36 + kw + 4];
            }
            #pragma unroll
            for (int mt = 0; mt < 4; mt++)
                #pragma unroll
                for (int nt = 0; nt < 4; nt++) {
                    asm volatile(
                        "mma.sync.aligned.m16n8k8.row.col.f32.tf32.tf32.f32 "
                        "{%0,%1,%2,%3}, {%4,%5,%6,%7}, {%8,%9}, {%0,%1,%2,%3};\n"
                        : "+f"(acc[mt][nt][0]), "+f"(acc[mt][nt][1]),
                          "+f"(acc[mt][nt][2]), "+f"(acc[mt][nt][3])
                        : "r"(af[mt][0]), "r"(af[mt][1]), "r"(af[mt][2]), "r"(af[mt][3]),
                          "r"(bfr[nt][0]), "r"(bfr[nt][1]));
                }
        }
        __syncthreads();
    }

    if (MODE == 2) {
        const bool isT = (n0 >= 768);
        const long dstBase = isT ? O_T2 : O_H2;
        const int  colOff  = isT ? 768 : 0;
        #pragma unroll
        for (int mt = 0; mt < 4; mt++) {
            #pragma unroll
            for (int half = 0; half < 2; half++) {
                int row = m0 + mwo + mt * 16 + g + half * 8;
                int b   = row >> 10;
                int hi  = hts[row * 2];
                int ti  = hts[row * 2 + 1];
                float maskf = (hi + ti) != 0 ? 1.f : 0.f;
                long erow = (long)(b * Ec + (isT ? ti : hi)) * 1536;
                #pragma unroll
                for (int nt = 0; nt < 4; nt++) {
                    int col = n0 + nwo + nt * 8 + tig * 2;
                    float2 e  = *reinterpret_cast<const float2*>(&g_buf[O_EHHT + erow + col]);
                    float2 bb = *reinterpret_cast<const float2*>(&g_buf[O_BIAS + col]);
                    float v0 = tanhf(acc[mt][nt][half * 2 + 0] + maskf * e.x + bb.x);
                    float v1 = tanhf(acc[mt][nt][half * 2 + 1] + maskf * e.y + bb.y);
                    *reinterpret_cast<float2*>(
                        &g_buf[dstBase + (long)row * Dc + col - colOff]) = make_float2(v0, v1);
                }
            }
        }
    } else {
        #pragma unroll
        for (int mt = 0; mt < 4; mt++) {
            int row = m0 + mwo + mt * 16 + g;
            #pragma unroll
            for (int nt = 0; nt < 4; nt++) {
                int col = n0 + nwo + nt * 8 + tig * 2;
                float2 v0 = make_float2(acc[mt][nt][0], acc[mt][nt][1]);
                float2 v1 = make_float2(acc[mt][nt][2], acc[mt][nt][3]);
                if (MODE == 1) {
                    v0.x = f2tf(v0.x); v0.y = f2tf(v0.y);
                    v1.x = f2tf(v1.x); v1.y = f2tf(v1.y);
                }
                *reinterpret_cast<float2*>(&C[(long)row * N + col])       = v0;
                *reinterpret_cast<float2*>(&C[(long)(row + 8) * N + col]) = v1;
            }
        }
    }
}

// ---------------- K9 fused (R9 form): bin_res += h2-tile · (t2-tile @ Wb^T) ----------------
__global__ __launch_bounds__(256) void k_binred(const float* __restrict__ Wbin,
                                                float* __restrict__ out)
{
    int mt = blockIdx.x;
    int n  = blockIdx.y;
    int o  = blockIdx.z;
    __shared__ float sA[64][65];
    __shared__ float sW[64][65];
    int tid = threadIdx.x;

    #pragma unroll
    for (int q = 0; q < 4; q++) {
        int idx = tid + q * 256;
        int r   = idx >> 4;
        int c4  = idx & 15;
        float4 v = *reinterpret_cast<const float4*>(
            &g_buf[O_T2 + (long)(mt * 64 + r) * Dc + n * 64 + c4 * 4]);
        sA[r][c4 * 4 + 0] = v.x;
        sA[r][c4 * 4 + 1] = v.y;
        sA[r][c4 * 4 + 2] = v.z;
        sA[r][c4 * 4 + 3] = v.w;
        float4 w = *reinterpret_cast<const float4*>(
            &Wbin[(long)o * (Dc * BSc) + n * 4096 + r * 64 + c4 * 4]);
        sW[c4 * 4 + 0][r] = w.x;
        sW[c4 * 4 + 1][r] = w.y;
        sW[c4 * 4 + 2][r] = w.z;
        sW[c4 * 4 + 3][r] = w.w;
    }
    __syncthreads();

    int tx = tid & 15, ty = tid >> 4;
    float acc[4][4];
    #pragma unroll
    for (int i = 0; i < 4; i++)
        #pragma unroll
        for (int j = 0; j < 4; j++) acc[i][j] = 0.f;

    #pragma unroll 8
    for (int k = 0; k < 64; k++) {
        float ar[4], br[4];
        #pragma unroll
        for (int r = 0; r < 4; r++) ar[r] = sA[ty * 4 + r][k];
        #pragma unroll
        for (int c = 0; c < 4; c++) br[c] = sW[k][tx * 4 + c];
        #pragma unroll
        for (int r = 0; r < 4; r++)
            #pragma unroll
            for (int c = 0; c < 4; c++)
                acc[r][c] = fmaf(ar[r], br[c], acc[r][c]);
    }

    float part[4];
    #pragma unroll
    for (int r = 0; r < 4; r++) {
        float4 h = *reinterpret_cast<const float4*>(
            &g_buf[O_H2 + (long)(mt * 64 + ty * 4 + r) * Dc + n * 64 + tx * 4]);
        float p;
        p = fmaf(acc[r][0], h.x, 0.f);
        p = fmaf(acc[r][1], h.y, p);
        p = fmaf(acc[r][2], h.z, p);
        p = fmaf(acc[r][3], h.w, p);
        part[r] = p;
    }
    #pragma unroll
    for (int m = 8; m > 0; m >>= 1) {
        #pragma unroll
        for (int r = 0; r < 4; r++)
            part[r] += __shfl_xor_sync(0xffffffffu, part[r], m);
    }
    if (tx == 0) {
        #pragma unroll
        for (int r = 0; r < 4; r++)
            atomicAdd(&out[(mt * 64 + ty * 4 + r) * 2 + o], part[r]);
    }
}

// ---------------- host launch ----------------
extern "C" void kernel_launch(void* const* d_in, const int* in_sizes, int n_in,
                              void* d_out, int out_size)
{
    const float* ctx  = (const float*)d_in[0];
    const float* att  = (const float*)d_in[1];
    const float* mm   = (const float*)d_in[2];
    const float* em   = (const float*)d_in[3];
    const int*   hts  = (const int*)d_in[4];
    const float* Wh   = (const float*)d_in[5];
    const float* bh   = (const float*)d_in[6];
    const float* Whc  = (const float*)d_in[7];
    const float* bhc  = (const float*)d_in[8];
    const float* Wt   = (const float*)d_in[9];
    const float* bt   = (const float*)d_in[10];
    const float* Wtc  = (const float*)d_in[11];
    const float* btc  = (const float*)d_in[12];
    const float* Wbin = (const float*)d_in[13];
    const float* bbin = (const float*)d_in[14];
    float* out = (float*)d_out;

    float* buf = nullptr;
    cudaGetSymbolAddress((void**)&buf, g_buf);

    cudaFuncSetAttribute(tc_gemm<0>, cudaFuncAttributeMaxDynamicSharedMemorySize, TC_SMEM);
    cudaFuncSetAttribute(tc_gemm<1>, cudaFuncAttributeMaxDynamicSharedMemorySize, TC_SMEM);
    cudaFuncSetAttribute(tc_gemm<2>, cudaFuncAttributeMaxDynamicSharedMemorySize, TC_SMEM);

    // stage 1: fused independent prep (entity | emnorm | w2tf | ctxT)
    k_prep1<<<P1_TOTAL, 256>>>(ctx, em, mm, Whc, Wtc, Wh, Wt);

    // stage 2: fused (ent2tf+bias+outinit | entatt)
    k_prep2<<<P2_TOTAL, 256>>>(att, bh, bhc, bt, btc, bbin, out);

    // stage 2b: ctx_att (depends on entatt)
    k_ctxatt<<<Bc * Pc, 256>>>(hts);

    // stage 3: GEMMs (tf32 mma.sync, 128x128 tiles — proven R9 config)
    tc_gemm<0><<<dim3(1536 / 128, 2, 1), 256, TC_SMEM>>>(
        buf + O_ETF, buf + O_WTF + 2 * SZ_W, buf + O_EHHT, 256, 1536, Dc, 0, 0, 0, nullptr);

    tc_gemm<1><<<dim3(Dc / 128, Pc / 128, Bc), 256, TC_SMEM>>>(
        buf + O_CTXATT, buf + O_CTXT, buf + O_CI,
        Pc, Dc, Lc, (long)Pc * Lc, (long)Dc * Lc, (long)Pc * Dc, nullptr);

    tc_gemm<2><<<dim3(1536 / 128, (Bc * Pc) / 128, 1), 256, TC_SMEM>>>(
        buf + O_CI, buf + O_WTF, nullptr, Bc * Pc, 1536, Dc, 0, 0, 0, hts);

    // stage 4: fused grouped bilinear (1536 blocks)
    k_binred<<<dim3((Bc * Pc) / 64, NBc, 2), 256>>>(Wbin, out);
}

// round 15
// speedup vs baseline: 1.1400x; 1.0702x over previous
#include <cuda_runtime.h>
#include <cuda_bf16.h>
#include <math.h>
#include <stdint.h>

// Problem constants
#define Bc 4
#define Lc 1024
#define Dc 768
#define Hc 12
#define Mc 96
#define Ec 48
#define Pc 1024
#define BSc 64
#define NBc 12

// ---------------- scratch (single device global, no allocation) ----------------
constexpr long SZ_ENTITY  = (long)Bc * Ec * Dc;
constexpr long SZ_ENTATT  = (long)Bc * Hc * Ec * Lc;
constexpr long SZ_CTXATT  = (long)Bc * Pc * Lc;
constexpr long SZ_CTXT    = (long)Bc * Dc * Lc;
constexpr long SZ_BPD     = (long)Bc * Pc * Dc;
constexpr long SZ_W       = (long)Dc * Dc;

constexpr long O_ENTITY  = 0;
constexpr long O_ENTATT  = O_ENTITY + SZ_ENTITY;
constexpr long O_CTXATT  = O_ENTATT + SZ_ENTATT;     // tf32-rounded fp32
constexpr long O_CTXT    = O_CTXATT + SZ_CTXATT;     // tf32-rounded fp32 [B][D][L]
constexpr long O_CI      = O_CTXT + SZ_CTXT;         // tf32-rounded fp32
constexpr long O_EHHT    = O_CI + SZ_BPD;            // [256][1536]: entity@[Wh;Wt]^T
constexpr long O_BIAS    = O_EHHT + 256 * 1536;      // [1536]: bh+bhc | bt+btc
constexpr long O_WTF     = O_BIAS + 1536;            // 4 weights tf32 [N][K]: Whc,Wtc,Wh,Wt
constexpr long O_ETF     = O_WTF + 4 * SZ_W;         // entity tf32 padded [256][D]
constexpr long O_H2      = O_ETF + 256 * Dc;
constexpr long O_T2      = O_H2 + SZ_BPD;
constexpr long O_TOTAL   = O_T2 + SZ_BPD;

__device__ __align__(16) float g_buf[O_TOTAL];
__device__ int   g_nz_idx[(long)Bc * Ec * Lc];
__device__ float g_nz_w[(long)Bc * Ec * Lc];
__device__ int   g_nz_cnt[Bc * Ec];

__device__ __forceinline__ float f2tf(float f)
{
    unsigned r;
    asm("cvt.rna.tf32.f32 %0, %1;" : "=r"(r) : "f"(f));
    return __uint_as_float(r);
}

// ---------------- shared-memory union for the fused prep1 kernel ----------------
struct SEnt  { int mc; int midx[Mc]; float mw[Mc]; int lc; int lidx[Lc]; float lw[Lc]; };
struct SNorm { int mc; int midx[Mc]; float mw[Mc]; float tok[Lc]; float red[256]; float inv; };
struct SCtxT { float t[32][33]; };

// grid layout for prep1 (all bodies 256 threads, mutually independent):
#define P1_ENTITY_END  192
#define P1_EMNORM_END  384
#define P1_W2TF_END    (384 + 2304)
#define P1_TOTAL       (2688 + 3072)

__device__ void body_entity(void* smem, int be,
                            const float* __restrict__ ctx, const float* __restrict__ em,
                            const float* __restrict__ mm)
{
    SEnt* s = reinterpret_cast<SEnt*>(smem);
    int b = be / Ec;

    if (threadIdx.x < 32) {
        int cnt = 0;
        for (int base = 0; base < Mc; base += 32) {
            int m = base + threadIdx.x;
            float w = em[(long)be * Mc + m];
            unsigned msk = __ballot_sync(0xffffffffu, w != 0.f);
            if (w != 0.f) {
                int pos = cnt + __popc(msk & ((1u << threadIdx.x) - 1u));
                s->midx[pos] = m;
                s->mw[pos]   = w;
            }
            cnt += __popc(msk);
        }
        if (threadIdx.x == 0) s->mc = cnt;
    }
    __syncthreads();
    int mc = s->mc;

    float eacc[3] = {0.f, 0.f, 0.f};
    for (int j = 0; j < mc; j++) {
        if (threadIdx.x < 32) {
            const float* mrow = mm + ((long)b * Mc + s->midx[j]) * Lc;
            int cnt = 0;
            for (int base = 0; base < Lc; base += 32) {
                int l = base + threadIdx.x;
                float w = mrow[l];
                unsigned msk = __ballot_sync(0xffffffffu, w != 0.f);
                if (w != 0.f) {
                    int pos = cnt + __popc(msk & ((1u << threadIdx.x) - 1u));
                    s->lidx[pos] = l;
                    s->lw[pos]   = w;
                }
                cnt += __popc(msk);
            }
            if (threadIdx.x == 0) s->lc = cnt;
        }
        __syncthreads();
        int lc = s->lc;
        float wj = s->mw[j];
        #pragma unroll
        for (int q = 0; q < 3; q++) {
            int d = threadIdx.x + q * 256;
            float a = 0.f;
            for (int i = 0; i < lc; i++)
                a += s->lw[i] * ctx[((long)b * Lc + s->lidx[i]) * Dc + d];
            eacc[q] += wj * expf(a);
        }
        __syncthreads();
    }
    #pragma unroll
    for (int q = 0; q < 3; q++) {
        int d = threadIdx.x + q * 256;
        g_buf[O_ENTITY + (long)be * Dc + d] = (mc == 0) ? 0.f : logf(eacc[q]);
    }
}

__device__ void body_emnorm(void* smem, int be,
                            const float* __restrict__ em, const float* __restrict__ mm)
{
    SNorm* s = reinterpret_cast<SNorm*>(smem);
    int b = be / Ec;

    if (threadIdx.x < 32) {
        int cnt = 0;
        for (int base = 0; base < Mc; base += 32) {
            int m = base + threadIdx.x;
            float w = em[(long)be * Mc + m];
            unsigned msk = __ballot_sync(0xffffffffu, w != 0.f);
            if (w != 0.f) {
                int pos = cnt + __popc(msk & ((1u << threadIdx.x) - 1u));
                s->midx[pos] = m;
                s->mw[pos]   = w;
            }
            cnt += __popc(msk);
        }
        if (threadIdx.x == 0) s->mc = cnt;
    }
    __syncthreads();
    int mc = s->mc;

    float part = 0.f;
    for (int l = threadIdx.x; l < Lc; l += 256) {
        float a = 0.f;
        for (int j = 0; j < mc; j++)
            a += s->mw[j] * mm[((long)b * Mc + s->midx[j]) * Lc + l];
        s->tok[l] = a;
        part += a;
    }
    s->red[threadIdx.x] = part;
    __syncthreads();
    for (int st = 128; st > 0; st >>= 1) {
        if (threadIdx.x < st) s->red[threadIdx.x] += s->red[threadIdx.x + st];
        __syncthreads();
    }
    if (threadIdx.x == 0) s->inv = 1.f / (s->red[0] + 1e-20f);
    __syncthreads();
    float inv = s->inv;

    if (threadIdx.x < 32) {
        int cnt = 0;
        for (int base = 0; base < Lc; base += 32) {
            int l = base + threadIdx.x;
            float v = s->tok[l];
            unsigned msk = __ballot_sync(0xffffffffu, v != 0.f);
            if (v != 0.f) {
                int pos = cnt + __popc(msk & ((1u << threadIdx.x) - 1u));
                g_nz_idx[(long)be * Lc + pos] = l;
                g_nz_w[(long)be * Lc + pos]   = v * inv;
            }
            cnt += __popc(msk);
        }
        if (threadIdx.x == 0) g_nz_cnt[be] = cnt;
    }
}

__device__ void body_w2tf(int blk, const float* __restrict__ W0, const float* __restrict__ W1,
                          const float* __restrict__ W2, const float* __restrict__ W3)
{
    int wsel = blk / 576;
    int bx   = blk % 576;
    const float* W = (wsel == 0) ? W0 : (wsel == 1) ? W1 : (wsel == 2) ? W2 : W3;
    float* D = &g_buf[O_WTF + (long)wsel * SZ_W];
    long i = ((long)bx * 256 + threadIdx.x) * 4;
    float4 v = *reinterpret_cast<const float4*>(&W[i]);
    v.x = f2tf(v.x); v.y = f2tf(v.y); v.z = f2tf(v.z); v.w = f2tf(v.w);
    *reinterpret_cast<float4*>(&D[i]) = v;
}

__device__ void body_ctxT(void* smem, int blk, const float* __restrict__ ctx)
{
    SCtxT* s = reinterpret_cast<SCtxT*>(smem);
    int bx = blk % 24;
    int by = (blk / 24) % 32;
    int b  = blk / (24 * 32);
    int tx = threadIdx.x & 31;
    int ty = threadIdx.x >> 5;
    const float* W = ctx + (long)b * Lc * Dc;
    float* O = &g_buf[O_CTXT + (long)b * Dc * Lc];
    int x  = bx * 32 + tx;
    int y0 = by * 32;
    for (int i = ty; i < 32; i += 8)
        s->t[i][tx] = W[(long)(y0 + i) * Dc + x];
    __syncthreads();
    int x2 = by * 32 + tx;
    for (int i = ty; i < 32; i += 8)
        O[(long)(bx * 32 + i) * Lc + x2] = f2tf(s->t[tx][i]);
}

__global__ __launch_bounds__(256) void k_prep1(
    const float* __restrict__ ctx, const float* __restrict__ em, const float* __restrict__ mm,
    const float* __restrict__ W0, const float* __restrict__ W1,
    const float* __restrict__ W2, const float* __restrict__ W3)
{
    __shared__ __align__(16) char pool[sizeof(SEnt)];
    int blk = blockIdx.x;
    if (blk < P1_ENTITY_END) {
        body_entity(pool, blk, ctx, em, mm);
    } else if (blk < P1_EMNORM_END) {
        body_emnorm(pool, blk - P1_ENTITY_END, em, mm);
    } else if (blk < P1_W2TF_END) {
        body_w2tf(blk - P1_EMNORM_END, W0, W1, W2, W3);
    } else {
        body_ctxT(pool, blk - P1_W2TF_END, ctx);
    }
}

// ---------------- prep2: ent2tf+bias+outinit | entatt | EHHT zero (independent) ----------------
// grid: [0,192) ent2tf ; [192, 2496) entatt ; [2496, 2880) zero EHHT
#define P2_ENT2TF_END 192
#define P2_ENTATT_END (192 + 2304)
#define P2_TOTAL      (192 + 2304 + 384)

__device__ void body_ent2tf(int blk,
                            const float* __restrict__ bh, const float* __restrict__ bhc,
                            const float* __restrict__ bt, const float* __restrict__ btc,
                            const float* __restrict__ bbin, float* __restrict__ out)
{
    long i = ((long)blk * 256 + threadIdx.x) * 4;
    int row = (int)(i / Dc);
    float4 v = make_float4(0.f, 0.f, 0.f, 0.f);
    if (row < Bc * Ec) {
        v = *reinterpret_cast<const float4*>(&g_buf[O_ENTITY + i]);
        v.x = f2tf(v.x); v.y = f2tf(v.y); v.z = f2tf(v.z); v.w = f2tf(v.w);
    }
    *reinterpret_cast<float4*>(&g_buf[O_ETF + i]) = v;
    int t = blk * 256 + threadIdx.x;
    if (t < 768)        g_buf[O_BIAS + t] = bh[t] + bhc[t];
    else if (t < 1536)  g_buf[O_BIAS + t] = bt[t - 768] + btc[t - 768];
    if (t < Bc * Pc * 2) out[t] = bbin[t & 1];
}

__device__ void body_entatt(int id, const float* __restrict__ att)
{
    int e  = id % Ec;
    int bh = id / Ec;
    int b  = bh / Hc;
    int be = b * Ec + e;
    int cnt = g_nz_cnt[be];
    int tid = threadIdx.x;

    float4 acc = make_float4(0.f, 0.f, 0.f, 0.f);
    for (int j = 0; j < cnt; j++) {
        int   l = g_nz_idx[(long)be * Lc + j];
        float w = g_nz_w[(long)be * Lc + j];
        float4 rv = reinterpret_cast<const float4*>(att + ((long)bh * Lc + l) * Lc)[tid];
        acc.x += w * rv.x;
        acc.y += w * rv.y;
        acc.z += w * rv.z;
        acc.w += w * rv.w;
    }
    reinterpret_cast<float4*>(&g_buf[O_ENTATT + (long)id * Lc])[tid] = acc;
}

__global__ __launch_bounds__(256) void k_prep2(
    const float* __restrict__ att,
    const float* __restrict__ bh, const float* __restrict__ bhc,
    const float* __restrict__ bt, const float* __restrict__ btc,
    const float* __restrict__ bbin, float* __restrict__ out)
{
    int blk = blockIdx.x;
    if (blk < P2_ENT2TF_END) {
        body_ent2tf(blk, bh, bhc, bt, btc, bbin, out);
    } else if (blk < P2_ENTATT_END) {
        body_entatt(blk - P2_ENT2TF_END, att);
    } else {
        long i = ((long)(blk - P2_ENTATT_END) * 256 + threadIdx.x) * 4;
        *reinterpret_cast<float4*>(&g_buf[O_EHHT + i]) = make_float4(0.f, 0.f, 0.f, 0.f);
    }
}

// ---------------- K5: ctx_att (normalized, pre-masked) -> tf32, float4 ----------------
__global__ void k_ctxatt(const int* __restrict__ hts)
{
    int bp = blockIdx.x;
    int b  = bp / Pc;
    int hi = hts[bp * 2];
    int ti = hts[bp * 2 + 1];
    float maskf = (hi + ti) != 0 ? 1.f : 0.f;
    int tid = threadIdx.x;

    const float4* ph = reinterpret_cast<const float4*>(
        &g_buf[O_ENTATT + ((long)b * Hc * Ec + hi) * Lc]);
    const float4* pt = reinterpret_cast<const float4*>(
        &g_buf[O_ENTATT + ((long)b * Hc * Ec + ti) * Lc]);
    const long step4 = (long)Ec * Lc / 4;

    float4 v = make_float4(0.f, 0.f, 0.f, 0.f);
    #pragma unroll
    for (int h = 0; h < Hc; h++) {
        float4 a = ph[h * step4 + tid];
        float4 c = pt[h * step4 + tid];
        v.x += a.x * c.x;
        v.y += a.y * c.y;
        v.z += a.z * c.z;
        v.w += a.w * c.w;
    }
    float part = (v.x + v.y) + (v.z + v.w);

    __shared__ float s_red[256];
    __shared__ float s_inv;
    s_red[tid] = part;
    __syncthreads();
    for (int s = 128; s > 0; s >>= 1) {
        if (tid < s) s_red[tid] += s_red[tid + s];
        __syncthreads();
    }
    if (tid == 0) s_inv = maskf / (s_red[0] + 1e-20f);
    __syncthreads();
    float inv = s_inv;
    float4 o;
    o.x = f2tf(v.x * inv);
    o.y = f2tf(v.y * inv);
    o.z = f2tf(v.z * inv);
    o.w = f2tf(v.w * inv);
    reinterpret_cast<float4*>(&g_buf[O_CTXATT + (long)bp * Lc])[tid] = o;
}

// ================= tf32 mma.sync GEMM (proven R9 config) =================
// MODE 0: fp32 out. MODE 1: tf32-rounded out. MODE 2: fused act epilogue.
// MODE 3: split-K (8-way, blockIdx.z = K segment), fp32 atomicAdd into C.
__device__ __forceinline__ uint32_t smem_u32(const void* p)
{
    uint32_t a;
    asm("{ .reg .u64 t; cvta.to.shared.u64 t, %1; cvt.u32.u64 %0, t; }" : "=r"(a) : "l"(p));
    return a;
}

#define TC_ROWB   144
#define TC_STAGE  (128 * TC_ROWB)
#define TC_SMEM   (4 * TC_STAGE)
#define SPLITK    8

template <int MODE>
__global__ __launch_bounds__(256) void tc_gemm(
    const float* __restrict__ A, const float* __restrict__ B, float* __restrict__ C,
    int M, int N, int K, long sA, long sB, long sC, const int* __restrict__ hts)
{
    extern __shared__ __align__(16) char smem[];
    if (MODE == 3) {
        int seg = K / SPLITK;
        A += (long)blockIdx.z * seg;     // column offset into K
        B += (long)blockIdx.z * seg;
    } else {
        A += (long)blockIdx.z * sA;
        B += (long)blockIdx.z * sB;
        C += (long)blockIdx.z * sC;
    }

    const uint32_t sb = smem_u32(smem);
    const int tid  = threadIdx.x;
    const int lane = tid & 31;
    const int wid  = tid >> 5;
    const int g    = lane >> 2;
    const int tig  = lane & 3;
    const int mwo  = (wid >> 2) * 64;
    const int nwo  = (wid & 3) * 32;
    const int m0   = blockIdx.y * 128;
    const int n0   = blockIdx.x * 128;

    const int crow = tid >> 1;
    const int cseg = (tid & 1) * 4;

    float acc[4][4][4];
    #pragma unroll
    for (int mt = 0; mt < 4; mt++)
        #pragma unroll
        for (int nt = 0; nt < 4; nt++)
            #pragma unroll
            for (int q = 0; q < 4; q++) acc[mt][nt][q] = 0.f;

    const int nch = (MODE == 3) ? (K >> 5) / SPLITK : (K >> 5);

    auto issue = [&](int c) {
        int s = c & 1;
        int k0 = c << 5;
        uint32_t da = sb + s * (2 * TC_STAGE) + crow * TC_ROWB;
        const float* pa = A + (long)(m0 + crow) * K + k0;
        #pragma unroll
        for (int j = 0; j < 4; j++)
            asm volatile("cp.async.cg.shared.global [%0], [%1], 16;"
                         :: "r"(da + (cseg + j) * 16), "l"(pa + (cseg + j) * 4));
        uint32_t db = da + TC_STAGE;
        const float* pb = B + (long)(n0 + crow) * K + k0;
        #pragma unroll
        for (int j = 0; j < 4; j++)
            asm volatile("cp.async.cg.shared.global [%0], [%1], 16;"
                         :: "r"(db + (cseg + j) * 16), "l"(pb + (cseg + j) * 4));
        asm volatile("cp.async.commit_group;" ::: "memory");
    };

    issue(0);
    for (int c = 0; c < nch; c++) {
        if (c + 1 < nch) {
            issue(c + 1);
            asm volatile("cp.async.wait_group 1;" ::: "memory");
        } else {
            asm volatile("cp.async.wait_group 0;" ::: "memory");
        }
        __syncthreads();

        const uint32_t* Aw = reinterpret_cast<const uint32_t*>(smem + (c & 1) * 2 * TC_STAGE);
        const uint32_t* Bw = reinterpret_cast<const uint32_t*>(smem + (c & 1) * 2 * TC_STAGE + TC_STAGE);

        #pragma unroll
        for (int ks = 0; ks < 4; ks++) {
            const int kw = ks * 8 + tig;
            uint32_t af[4][4], bfr[4][2];
            #pragma unroll
            for (int mt = 0; mt < 4; mt++) {
                int r = mwo + mt * 16 + g;
                af[mt][0] = Aw[r * 36 + kw];
                af[mt][1] = Aw[(r + 8) * 36 + kw];
                af[mt][2] = Aw[r * 36 + kw + 4];
                af[mt][3] = Aw[(r + 8) * 36 + kw + 4];
            }
            #pragma unroll
            for (int nt = 0; nt < 4; nt++) {
                int cc = nwo + nt * 8 + g;
                bfr[nt][0] = Bw[cc * 36 + kw];
                bfr[nt][1] = Bw[cc * 36 + kw + 4];
            }
            #pragma unroll
            for (int mt = 0; mt < 4; mt++)
                #pragma unroll
                for (int nt = 0; nt < 4; nt++) {
                    asm volatile(
                        "mma.sync.aligned.m16n8k8.row.col.f32.tf32.tf32.f32 "
                        "{%0,%1,%2,%3}, {%4,%5,%6,%7}, {%8,%9}, {%0,%1,%2,%3};\n"
                        : "+f"(acc[mt][nt][0]), "+f"(acc[mt][nt][1]),
                          "+f"(acc[mt][nt][2]), "+f"(acc[mt][nt][3])
                        : "r"(af[mt][0]), "r"(af[mt][1]), "r"(af[mt][2]), "r"(af[mt][3]),
                          "r"(bfr[nt][0]), "r"(bfr[nt][1]));
                }
        }
        __syncthreads();
    }

    if (MODE == 3) {
        #pragma unroll
        for (int mt = 0; mt < 4; mt++) {
            int row = m0 + mwo + mt * 16 + g;
            #pragma unroll
            for (int nt = 0; nt < 4; nt++) {
                int col = n0 + nwo + nt * 8 + tig * 2;
                atomicAdd(&C[(long)row * N + col],           acc[mt][nt][0]);
                atomicAdd(&C[(long)row * N + col + 1],       acc[mt][nt][1]);
                atomicAdd(&C[(long)(row + 8) * N + col],     acc[mt][nt][2]);
                atomicAdd(&C[(long)(row + 8) * N + col + 1], acc[mt][nt][3]);
            }
        }
    } else if (MODE == 2) {
        const bool isT = (n0 >= 768);
        const long dstBase = isT ? O_T2 : O_H2;
        const int  colOff  = isT ? 768 : 0;
        #pragma unroll
        for (int mt = 0; mt < 4; mt++) {
            #pragma unroll
            for (int half = 0; half < 2; half++) {
                int row = m0 + mwo + mt * 16 + g + half * 8;
                int b   = row >> 10;
                int hi  = hts[row * 2];
                int ti  = hts[row * 2 + 1];
                float maskf = (hi + ti) != 0 ? 1.f : 0.f;
                long erow = (long)(b * Ec + (isT ? ti : hi)) * 1536;
                #pragma unroll
                for (int nt = 0; nt < 4; nt++) {
                    int col = n0 + nwo + nt * 8 + tig * 2;
                    float2 e  = *reinterpret_cast<const float2*>(&g_buf[O_EHHT + erow + col]);
                    float2 bb = *reinterpret_cast<const float2*>(&g_buf[O_BIAS + col]);
                    float v0 = tanhf(acc[mt][nt][half * 2 + 0] + maskf * e.x + bb.x);
                    float v1 = tanhf(acc[mt][nt][half * 2 + 1] + maskf * e.y + bb.y);
                    *reinterpret_cast<float2*>(
                        &g_buf[dstBase + (long)row * Dc + col - colOff]) = make_float2(v0, v1);
                }
            }
        }
    } else {
        #pragma unroll
        for (int mt = 0; mt < 4; mt++) {
            int row = m0 + mwo + mt * 16 + g;
            #pragma unroll
            for (int nt = 0; nt < 4; nt++) {
                int col = n0 + nwo + nt * 8 + tig * 2;
                float2 v0 = make_float2(acc[mt][nt][0], acc[mt][nt][1]);
                float2 v1 = make_float2(acc[mt][nt][2], acc[mt][nt][3]);
                if (MODE == 1) {
                    v0.x = f2tf(v0.x); v0.y = f2tf(v0.y);
                    v1.x = f2tf(v1.x); v1.y = f2tf(v1.y);
                }
                *reinterpret_cast<float2*>(&C[(long)row * N + col])       = v0;
                *reinterpret_cast<float2*>(&C[(long)(row + 8) * N + col]) = v1;
            }
        }
    }
}

// ---------------- K9 fused (R9 form): bin_res += h2-tile · (t2-tile @ Wb^T) ----------------
__global__ __launch_bounds__(256) void k_binred(const float* __restrict__ Wbin,
                                                float* __restrict__ out)
{
    int mt = blockIdx.x;
    int n  = blockIdx.y;
    int o  = blockIdx.z;
    __shared__ float sA[64][65];
    __shared__ float sW[64][65];
    int tid = threadIdx.x;

    #pragma unroll
    for (int q = 0; q < 4; q++) {
        int idx = tid + q * 256;
        int r   = idx >> 4;
        int c4  = idx & 15;
        float4 v = *reinterpret_cast<const float4*>(
            &g_buf[O_T2 + (long)(mt * 64 + r) * Dc + n * 64 + c4 * 4]);
        sA[r][c4 * 4 + 0] = v.x;
        sA[r][c4 * 4 + 1] = v.y;
        sA[r][c4 * 4 + 2] = v.z;
        sA[r][c4 * 4 + 3] = v.w;
        float4 w = *reinterpret_cast<const float4*>(
            &Wbin[(long)o * (Dc * BSc) + n * 4096 + r * 64 + c4 * 4]);
        sW[c4 * 4 + 0][r] = w.x;
        sW[c4 * 4 + 1][r] = w.y;
        sW[c4 * 4 + 2][r] = w.z;
        sW[c4 * 4 + 3][r] = w.w;
    }
    __syncthreads();

    int tx = tid & 15, ty = tid >> 4;
    float acc[4][4];
    #pragma unroll
    for (int i = 0; i < 4; i++)
        #pragma unroll
        for (int j = 0; j < 4; j++) acc[i][j] = 0.f;

    #pragma unroll 8
    for (int k = 0; k < 64; k++) {
        float ar[4], br[4];
        #pragma unroll
        for (int r = 0; r < 4; r++) ar[r] = sA[ty * 4 + r][k];
        #pragma unroll
        for (int c = 0; c < 4; c++) br[c] = sW[k][tx * 4 + c];
        #pragma unroll
        for (int r = 0; r < 4; r++)
            #pragma unroll
            for (int c = 0; c < 4; c++)
                acc[r][c] = fmaf(ar[r], br[c], acc[r][c]);
    }

    float part[4];
    #pragma unroll
    for (int r = 0; r < 4; r++) {
        float4 h = *reinterpret_cast<const float4*>(
            &g_buf[O_H2 + (long)(mt * 64 + ty * 4 + r) * Dc + n * 64 + tx * 4]);
        float p;
        p = fmaf(acc[r][0], h.x, 0.f);
        p = fmaf(acc[r][1], h.y, p);
        p = fmaf(acc[r][2], h.z, p);
        p = fmaf(acc[r][3], h.w, p);
        part[r] = p;
    }
    #pragma unroll
    for (int m = 8; m > 0; m >>= 1) {
        #pragma unroll
        for (int r = 0; r < 4; r++)
            part[r] += __shfl_xor_sync(0xffffffffu, part[r], m);
    }
    if (tx == 0) {
        #pragma unroll
        for (int r = 0; r < 4; r++)
            atomicAdd(&out[(mt * 64 + ty * 4 + r) * 2 + o], part[r]);
    }
}

// ---------------- host launch ----------------
extern "C" void kernel_launch(void* const* d_in, const int* in_sizes, int n_in,
                              void* d_out, int out_size)
{
    const float* ctx  = (const float*)d_in[0];
    const float* att  = (const float*)d_in[1];
    const float* mm   = (const float*)d_in[2];
    const float* em   = (const float*)d_in[3];
    const int*   hts  = (const int*)d_in[4];
    const float* Wh   = (const float*)d_in[5];
    const float* bh   = (const float*)d_in[6];
    const float* Whc  = (const float*)d_in[7];
    const float* bhc  = (const float*)d_in[8];
    const float* Wt   = (const float*)d_in[9];
    const float* bt   = (const float*)d_in[10];
    const float* Wtc  = (const float*)d_in[11];
    const float* btc  = (const float*)d_in[12];
    const float* Wbin = (const float*)d_in[13];
    const float* bbin = (const float*)d_in[14];
    float* out = (float*)d_out;

    float* buf = nullptr;
    cudaGetSymbolAddress((void**)&buf, g_buf);

    cudaFuncSetAttribute(tc_gemm<1>, cudaFuncAttributeMaxDynamicSharedMemorySize, TC_SMEM);
    cudaFuncSetAttribute(tc_gemm<2>, cudaFuncAttributeMaxDynamicSharedMemorySize, TC_SMEM);
    cudaFuncSetAttribute(tc_gemm<3>, cudaFuncAttributeMaxDynamicSharedMemorySize, TC_SMEM);

    // stage 1: fused independent prep (entity | emnorm | w2tf | ctxT)
    k_prep1<<<P1_TOTAL, 256>>>(ctx, em, mm, Whc, Wtc, Wh, Wt);

    // stage 2: fused (ent2tf+bias+outinit | entatt | EHHT zero)
    k_prep2<<<P2_TOTAL, 256>>>(att, bh, bhc, bt, btc, bbin, out);

    // stage 2b: ctx_att (depends on entatt)
    k_ctxatt<<<Bc * Pc, 256>>>(hts);

    // stage 3: GEMMs (tf32 mma.sync, 128x128 tiles)
    // entity @ [Wh;Wt]^T -> EHHT, split-K 8-way (tiny-M GEMM was latency-bound at grid=24)
    tc_gemm<3><<<dim3(1536 / 128, 2, SPLITK), 256, TC_SMEM>>>(
        buf + O_ETF, buf + O_WTF + 2 * SZ_W, buf + O_EHHT, 256, 1536, Dc, 0, 0, 0, nullptr);

    tc_gemm<1><<<dim3(Dc / 128, Pc / 128, Bc), 256, TC_SMEM>>>(
        buf + O_CTXATT, buf + O_CTXT, buf + O_CI,
        Pc, Dc, Lc, (long)Pc * Lc, (long)Dc * Lc, (long)Pc * Dc, nullptr);

    tc_gemm<2><<<dim3(1536 / 128, (Bc * Pc) / 128, 1), 256, TC_SMEM>>>(
        buf + O_CI, buf + O_WTF, nullptr, Bc * Pc, 1536, Dc, 0, 0, 0, hts);

    // stage 4: fused grouped bilinear (1536 blocks)
    k_binred<<<dim3((Bc * Pc) / 64, NBc, 2), 256>>>(Wbin, out);
}

// round 16
// speedup vs baseline: 1.2258x; 1.0752x over previous
#include <cuda_runtime.h>
#include <cuda_bf16.h>
#include <math.h>
#include <stdint.h>

// Problem constants
#define Bc 4
#define Lc 1024
#define Dc 768
#define Hc 12
#define Mc 96
#define Ec 48
#define Pc 1024
#define BSc 64
#define NBc 12

// ---------------- scratch (single device global, no allocation) ----------------
constexpr long SZ_ENTITY  = (long)Bc * Ec * Dc;
constexpr long SZ_ENTATT  = (long)Bc * Hc * Ec * Lc;
constexpr long SZ_CTXATT  = (long)Bc * Pc * Lc;
constexpr long SZ_CTXT    = (long)Bc * Dc * Lc;
constexpr long SZ_BPD     = (long)Bc * Pc * Dc;
constexpr long SZ_W       = (long)Dc * Dc;

constexpr long O_ENTITY  = 0;
constexpr long O_ENTATT  = O_ENTITY + SZ_ENTITY;
constexpr long O_CTXATT  = O_ENTATT + SZ_ENTATT;     // tf32-rounded fp32
constexpr long O_CTXT    = O_CTXATT + SZ_CTXATT;     // tf32-rounded fp32 [B][D][L]
constexpr long O_CI      = O_CTXT + SZ_CTXT;         // tf32-rounded fp32
constexpr long O_EHHT    = O_CI + SZ_BPD;            // [256][1536]: entity@[Wh;Wt]^T
constexpr long O_BIAS    = O_EHHT + 256 * 1536;      // [1536]: bh+bhc | bt+btc
constexpr long O_WTF     = O_BIAS + 1536;            // 4 weights tf32 [N][K]: Whc,Wtc,Wh,Wt
constexpr long O_ETF     = O_WTF + 4 * SZ_W;         // entity tf32 padded [256][D]
constexpr long O_H2      = O_ETF + 256 * Dc;
constexpr long O_T2      = O_H2 + SZ_BPD;
constexpr long O_TOTAL   = O_T2 + SZ_BPD;

__device__ __align__(16) float g_buf[O_TOTAL];
__device__ int   g_nz_idx[(long)Bc * Ec * Lc];
__device__ float g_nz_w[(long)Bc * Ec * Lc];
__device__ int   g_nz_cnt[Bc * Ec];

__device__ __forceinline__ float f2tf(float f)
{
    unsigned r;
    asm("cvt.rna.tf32.f32 %0, %1;" : "=r"(r) : "f"(f));
    return __uint_as_float(r);
}

// ---------------- shared-memory union for the fused prep1 kernel ----------------
struct SEnt  { int mc; int midx[Mc]; float mw[Mc]; int lc; int lidx[Lc]; float lw[Lc]; };
struct SNorm { int mc; int midx[Mc]; float mw[Mc]; float tok[Lc]; float red[256]; float inv; };
struct SCtxT { float t[32][33]; };

#define P1_ENTITY_END  192
#define P1_EMNORM_END  384
#define P1_W2TF_END    (384 + 2304)
#define P1_TOTAL       (2688 + 3072)

__device__ void body_entity(void* smem, int be,
                            const float* __restrict__ ctx, const float* __restrict__ em,
                            const float* __restrict__ mm)
{
    SEnt* s = reinterpret_cast<SEnt*>(smem);
    int b = be / Ec;

    if (threadIdx.x < 32) {
        int cnt = 0;
        for (int base = 0; base < Mc; base += 32) {
            int m = base + threadIdx.x;
            float w = em[(long)be * Mc + m];
            unsigned msk = __ballot_sync(0xffffffffu, w != 0.f);
            if (w != 0.f) {
                int pos = cnt + __popc(msk & ((1u << threadIdx.x) - 1u));
                s->midx[pos] = m;
                s->mw[pos]   = w;
            }
            cnt += __popc(msk);
        }
        if (threadIdx.x == 0) s->mc = cnt;
    }
    __syncthreads();
    int mc = s->mc;

    float eacc[3] = {0.f, 0.f, 0.f};
    for (int j = 0; j < mc; j++) {
        if (threadIdx.x < 32) {
            const float* mrow = mm + ((long)b * Mc + s->midx[j]) * Lc;
            int cnt = 0;
            for (int base = 0; base < Lc; base += 32) {
                int l = base + threadIdx.x;
                float w = mrow[l];
                unsigned msk = __ballot_sync(0xffffffffu, w != 0.f);
                if (w != 0.f) {
                    int pos = cnt + __popc(msk & ((1u << threadIdx.x) - 1u));
                    s->lidx[pos] = l;
                    s->lw[pos]   = w;
                }
                cnt += __popc(msk);
            }
            if (threadIdx.x == 0) s->lc = cnt;
        }
        __syncthreads();
        int lc = s->lc;
        float wj = s->mw[j];
        #pragma unroll
        for (int q = 0; q < 3; q++) {
            int d = threadIdx.x + q * 256;
            float a = 0.f;
            for (int i = 0; i < lc; i++)
                a += s->lw[i] * ctx[((long)b * Lc + s->lidx[i]) * Dc + d];
            eacc[q] += wj * expf(a);
        }
        __syncthreads();
    }
    #pragma unroll
    for (int q = 0; q < 3; q++) {
        int d = threadIdx.x + q * 256;
        g_buf[O_ENTITY + (long)be * Dc + d] = (mc == 0) ? 0.f : logf(eacc[q]);
    }
}

__device__ void body_emnorm(void* smem, int be,
                            const float* __restrict__ em, const float* __restrict__ mm)
{
    SNorm* s = reinterpret_cast<SNorm*>(smem);
    int b = be / Ec;

    if (threadIdx.x < 32) {
        int cnt = 0;
        for (int base = 0; base < Mc; base += 32) {
            int m = base + threadIdx.x;
            float w = em[(long)be * Mc + m];
            unsigned msk = __ballot_sync(0xffffffffu, w != 0.f);
            if (w != 0.f) {
                int pos = cnt + __popc(msk & ((1u << threadIdx.x) - 1u));
                s->midx[pos] = m;
                s->mw[pos]   = w;
            }
            cnt += __popc(msk);
        }
        if (threadIdx.x == 0) s->mc = cnt;
    }
    __syncthreads();
    int mc = s->mc;

    float part = 0.f;
    for (int l = threadIdx.x; l < Lc; l += 256) {
        float a = 0.f;
        for (int j = 0; j < mc; j++)
            a += s->mw[j] * mm[((long)b * Mc + s->midx[j]) * Lc + l];
        s->tok[l] = a;
        part += a;
    }
    s->red[threadIdx.x] = part;
    __syncthreads();
    for (int st = 128; st > 0; st >>= 1) {
        if (threadIdx.x < st) s->red[threadIdx.x] += s->red[threadIdx.x + st];
        __syncthreads();
    }
    if (threadIdx.x == 0) s->inv = 1.f / (s->red[0] + 1e-20f);
    __syncthreads();
    float inv = s->inv;

    if (threadIdx.x < 32) {
        int cnt = 0;
        for (int base = 0; base < Lc; base += 32) {
            int l = base + threadIdx.x;
            float v = s->tok[l];
            unsigned msk = __ballot_sync(0xffffffffu, v != 0.f);
            if (v != 0.f) {
                int pos = cnt + __popc(msk & ((1u << threadIdx.x) - 1u));
                g_nz_idx[(long)be * Lc + pos] = l;
                g_nz_w[(long)be * Lc + pos]   = v * inv;
            }
            cnt += __popc(msk);
        }
        if (threadIdx.x == 0) g_nz_cnt[be] = cnt;
    }
}

__device__ void body_w2tf(int blk, const float* __restrict__ W0, const float* __restrict__ W1,
                          const float* __restrict__ W2, const float* __restrict__ W3)
{
    int wsel = blk / 576;
    int bx   = blk % 576;
    const float* W = (wsel == 0) ? W0 : (wsel == 1) ? W1 : (wsel == 2) ? W2 : W3;
    float* D = &g_buf[O_WTF + (long)wsel * SZ_W];
    long i = ((long)bx * 256 + threadIdx.x) * 4;
    float4 v = *reinterpret_cast<const float4*>(&W[i]);
    v.x = f2tf(v.x); v.y = f2tf(v.y); v.z = f2tf(v.z); v.w = f2tf(v.w);
    *reinterpret_cast<float4*>(&D[i]) = v;
}

__device__ void body_ctxT(void* smem, int blk, const float* __restrict__ ctx)
{
    SCtxT* s = reinterpret_cast<SCtxT*>(smem);
    int bx = blk % 24;
    int by = (blk / 24) % 32;
    int b  = blk / (24 * 32);
    int tx = threadIdx.x & 31;
    int ty = threadIdx.x >> 5;
    const float* W = ctx + (long)b * Lc * Dc;
    float* O = &g_buf[O_CTXT + (long)b * Dc * Lc];
    int x  = bx * 32 + tx;
    int y0 = by * 32;
    for (int i = ty; i < 32; i += 8)
        s->t[i][tx] = W[(long)(y0 + i) * Dc + x];
    __syncthreads();
    int x2 = by * 32 + tx;
    for (int i = ty; i < 32; i += 8)
        O[(long)(bx * 32 + i) * Lc + x2] = f2tf(s->t[tx][i]);
}

__global__ __launch_bounds__(256) void k_prep1(
    const float* __restrict__ ctx, const float* __restrict__ em, const float* __restrict__ mm,
    const float* __restrict__ W0, const float* __restrict__ W1,
    const float* __restrict__ W2, const float* __restrict__ W3)
{
    __shared__ __align__(16) char pool[sizeof(SEnt)];
    int blk = blockIdx.x;
    if (blk < P1_ENTITY_END) {
        body_entity(pool, blk, ctx, em, mm);
    } else if (blk < P1_EMNORM_END) {
        body_emnorm(pool, blk - P1_ENTITY_END, em, mm);
    } else if (blk < P1_W2TF_END) {
        body_w2tf(blk - P1_EMNORM_END, W0, W1, W2, W3);
    } else {
        body_ctxT(pool, blk - P1_W2TF_END, ctx);
    }
}

// ---------------- prep2: ent2tf+bias+outinit | entatt | EHHT zero (independent) ----------------
#define P2_ENT2TF_END 192
#define P2_ENTATT_END (192 + 2304)
#define P2_TOTAL      (192 + 2304 + 384)

__device__ void body_ent2tf(int blk,
                            const float* __restrict__ bh, const float* __restrict__ bhc,
                            const float* __restrict__ bt, const float* __restrict__ btc,
                            const float* __restrict__ bbin, float* __restrict__ out)
{
    long i = ((long)blk * 256 + threadIdx.x) * 4;
    int row = (int)(i / Dc);
    float4 v = make_float4(0.f, 0.f, 0.f, 0.f);
    if (row < Bc * Ec) {
        v = *reinterpret_cast<const float4*>(&g_buf[O_ENTITY + i]);
        v.x = f2tf(v.x); v.y = f2tf(v.y); v.z = f2tf(v.z); v.w = f2tf(v.w);
    }
    *reinterpret_cast<float4*>(&g_buf[O_ETF + i]) = v;
    int t = blk * 256 + threadIdx.x;
    if (t < 768)        g_buf[O_BIAS + t] = bh[t] + bhc[t];
    else if (t < 1536)  g_buf[O_BIAS + t] = bt[t - 768] + btc[t - 768];
    if (t < Bc * Pc * 2) out[t] = bbin[t & 1];
}

__device__ void body_entatt(int id, const float* __restrict__ att)
{
    int e  = id % Ec;
    int bh = id / Ec;
    int b  = bh / Hc;
    int be = b * Ec + e;
    int cnt = g_nz_cnt[be];
    int tid = threadIdx.x;

    float4 acc = make_float4(0.f, 0.f, 0.f, 0.f);
    for (int j = 0; j < cnt; j++) {
        int   l = g_nz_idx[(long)be * Lc + j];
        float w = g_nz_w[(long)be * Lc + j];
        float4 rv = reinterpret_cast<const float4*>(att + ((long)bh * Lc + l) * Lc)[tid];
        acc.x += w * rv.x;
        acc.y += w * rv.y;
        acc.z += w * rv.z;
        acc.w += w * rv.w;
    }
    reinterpret_cast<float4*>(&g_buf[O_ENTATT + (long)id * Lc])[tid] = acc;
}

__global__ __launch_bounds__(256) void k_prep2(
    const float* __restrict__ att,
    const float* __restrict__ bh, const float* __restrict__ bhc,
    const float* __restrict__ bt, const float* __restrict__ btc,
    const float* __restrict__ bbin, float* __restrict__ out)
{
    int blk = blockIdx.x;
    if (blk < P2_ENT2TF_END) {
        body_ent2tf(blk, bh, bhc, bt, btc, bbin, out);
    } else if (blk < P2_ENTATT_END) {
        body_entatt(blk - P2_ENT2TF_END, att);
    } else {
        long i = ((long)(blk - P2_ENTATT_END) * 256 + threadIdx.x) * 4;
        *reinterpret_cast<float4*>(&g_buf[O_EHHT + i]) = make_float4(0.f, 0.f, 0.f, 0.f);
    }
}

// ---------------- K5: ctx_att (normalized, pre-masked) -> tf32, float4 ----------------
__global__ void k_ctxatt(const int* __restrict__ hts)
{
    int bp = blockIdx.x;
    int b  = bp / Pc;
    int hi = hts[bp * 2];
    int ti = hts[bp * 2 + 1];
    float maskf = (hi + ti) != 0 ? 1.f : 0.f;
    int tid = threadIdx.x;

    const float4* ph = reinterpret_cast<const float4*>(
        &g_buf[O_ENTATT + ((long)b * Hc * Ec + hi) * Lc]);
    const float4* pt = reinterpret_cast<const float4*>(
        &g_buf[O_ENTATT + ((long)b * Hc * Ec + ti) * Lc]);
    const long step4 = (long)Ec * Lc / 4;

    float4 v = make_float4(0.f, 0.f, 0.f, 0.f);
    #pragma unroll
    for (int h = 0; h < Hc; h++) {
        float4 a = ph[h * step4 + tid];
        float4 c = pt[h * step4 + tid];
        v.x += a.x * c.x;
        v.y += a.y * c.y;
        v.z += a.z * c.z;
        v.w += a.w * c.w;
    }
    float part = (v.x + v.y) + (v.z + v.w);

    __shared__ float s_red[256];
    __shared__ float s_inv;
    s_red[tid] = part;
    __syncthreads();
    for (int s = 128; s > 0; s >>= 1) {
        if (tid < s) s_red[tid] += s_red[tid + s];
        __syncthreads();
    }
    if (tid == 0) s_inv = maskf / (s_red[0] + 1e-20f);
    __syncthreads();
    float inv = s_inv;
    float4 o;
    o.x = f2tf(v.x * inv);
    o.y = f2tf(v.y * inv);
    o.z = f2tf(v.z * inv);
    o.w = f2tf(v.w * inv);
    reinterpret_cast<float4*>(&g_buf[O_CTXATT + (long)bp * Lc])[tid] = o;
}

// ================= tf32 mma.sync GEMM infrastructure =================
__device__ __forceinline__ uint32_t smem_u32(const void* p)
{
    uint32_t a;
    asm("{ .reg .u64 t; cvta.to.shared.u64 t, %1; cvt.u32.u64 %0, t; }" : "=r"(a) : "l"(p));
    return a;
}

#define TC_ROWB   144
#define TC_STAGE  (128 * TC_ROWB)
#define TC_SMEM   (4 * TC_STAGE)
#define SPLITK    8

// ---------------- fused GEMM1 (MODE1) + GEMM3 (split-K MODE3) in one launch -----------
// blocks [0,192):  ci[b] = ctx_att[b] @ ctxT[b], tf32-rounded out  (old grid 6x8x4)
// blocks [192,384): entity GEMM split-K, atomicAdd into EHHT        (old grid 12x2x8)
#define G13_SPLIT 192
#define G13_TOTAL 384

__global__ __launch_bounds__(256) void k_gemm13()
{
    extern __shared__ __align__(16) char smem[];
    const int blk = blockIdx.x;

    const float* A;
    const float* B;
    float* C;
    int N, K, nch, m0, n0;
    bool mode1;

    if (blk < G13_SPLIT) {
        int bx = blk % 6, by = (blk / 6) % 8, bz = blk / 48;
        A = &g_buf[O_CTXATT + (long)bz * Pc * Lc];
        B = &g_buf[O_CTXT + (long)bz * Dc * Lc];
        C = &g_buf[O_CI + (long)bz * Pc * Dc];
        N = Dc; K = Lc; nch = Lc >> 5;
        m0 = by * 128; n0 = bx * 128;
        mode1 = true;
    } else {
        int id = blk - G13_SPLIT;
        int bx = id % 12, by = (id / 12) % 2, bz = id / 24;
        int seg = Dc / SPLITK;               // 96
        A = &g_buf[O_ETF] + (long)bz * seg;  // column offset into K
        B = &g_buf[O_WTF + 2 * SZ_W] + (long)bz * seg;
        C = &g_buf[O_EHHT];
        N = 1536; K = Dc; nch = (Dc >> 5) / SPLITK;  // 3
        m0 = by * 128; n0 = bx * 128;
        mode1 = false;
    }

    const uint32_t sb = smem_u32(smem);
    const int tid  = threadIdx.x;
    const int lane = tid & 31;
    const int wid  = tid >> 5;
    const int g    = lane >> 2;
    const int tig  = lane & 3;
    const int mwo  = (wid >> 2) * 64;
    const int nwo  = (wid & 3) * 32;

    const int crow = tid >> 1;
    const int cseg = (tid & 1) * 4;

    float acc[4][4][4];
    #pragma unroll
    for (int mt = 0; mt < 4; mt++)
        #pragma unroll
        for (int nt = 0; nt < 4; nt++)
            #pragma unroll
            for (int q = 0; q < 4; q++) acc[mt][nt][q] = 0.f;

    auto issue = [&](int c) {
        int s = c & 1;
        int k0 = c << 5;
        uint32_t da = sb + s * (2 * TC_STAGE) + crow * TC_ROWB;
        const float* pa = A + (long)(m0 + crow) * K + k0;
        #pragma unroll
        for (int j = 0; j < 4; j++)
            asm volatile("cp.async.cg.shared.global [%0], [%1], 16;"
                         :: "r"(da + (cseg + j) * 16), "l"(pa + (cseg + j) * 4));
        uint32_t db = da + TC_STAGE;
        const float* pb = B + (long)(n0 + crow) * K + k0;
        #pragma unroll
        for (int j = 0; j < 4; j++)
            asm volatile("cp.async.cg.shared.global [%0], [%1], 16;"
                         :: "r"(db + (cseg + j) * 16), "l"(pb + (cseg + j) * 4));
        asm volatile("cp.async.commit_group;" ::: "memory");
    };

    issue(0);
    for (int c = 0; c < nch; c++) {
        if (c + 1 < nch) {
            issue(c + 1);
            asm volatile("cp.async.wait_group 1;" ::: "memory");
        } else {
            asm volatile("cp.async.wait_group 0;" ::: "memory");
        }
        __syncthreads();

        const uint32_t* Aw = reinterpret_cast<const uint32_t*>(smem + (c & 1) * 2 * TC_STAGE);
        const uint32_t* Bw = reinterpret_cast<const uint32_t*>(smem + (c & 1) * 2 * TC_STAGE + TC_STAGE);

        #pragma unroll
        for (int ks = 0; ks < 4; ks++) {
            const int kw = ks * 8 + tig;
            uint32_t af[4][4], bfr[4][2];
            #pragma unroll
            for (int mt = 0; mt < 4; mt++) {
                int r = mwo + mt * 16 + g;
                af[mt][0] = Aw[r * 36 + kw];
                af[mt][1] = Aw[(r + 8) * 36 + kw];
                af[mt][2] = Aw[r * 36 + kw + 4];
                af[mt][3] = Aw[(r + 8) * 36 + kw + 4];
            }
            #pragma unroll
            for (int nt = 0; nt < 4; nt++) {
                int cc = nwo + nt * 8 + g;
                bfr[nt][0] = Bw[cc * 36 + kw];
                bfr[nt][1] = Bw[cc * 36 + kw + 4];
            }
            #pragma unroll
            for (int mt = 0; mt < 4; mt++)
                #pragma unroll
                for (int nt = 0; nt < 4; nt++) {
                    asm volatile(
                        "mma.sync.aligned.m16n8k8.row.col.f32.tf32.tf32.f32 "
                        "{%0,%1,%2,%3}, {%4,%5,%6,%7}, {%8,%9}, {%0,%1,%2,%3};\n"
                        : "+f"(acc[mt][nt][0]), "+f"(acc[mt][nt][1]),
                          "+f"(acc[mt][nt][2]), "+f"(acc[mt][nt][3])
                        : "r"(af[mt][0]), "r"(af[mt][1]), "r"(af[mt][2]), "r"(af[mt][3]),
                          "r"(bfr[nt][0]), "r"(bfr[nt][1]));
                }
        }
        __syncthreads();
    }

    if (mode1) {
        #pragma unroll
        for (int mt = 0; mt < 4; mt++) {
            int row = m0 + mwo + mt * 16 + g;
            #pragma unroll
            for (int nt = 0; nt < 4; nt++) {
                int col = n0 + nwo + nt * 8 + tig * 2;
                float2 v0 = make_float2(f2tf(acc[mt][nt][0]), f2tf(acc[mt][nt][1]));
                float2 v1 = make_float2(f2tf(acc[mt][nt][2]), f2tf(acc[mt][nt][3]));
                *reinterpret_cast<float2*>(&C[(long)row * N + col])       = v0;
                *reinterpret_cast<float2*>(&C[(long)(row + 8) * N + col]) = v1;
            }
        }
    } else {
        #pragma unroll
        for (int mt = 0; mt < 4; mt++) {
            int row = m0 + mwo + mt * 16 + g;
            #pragma unroll
            for (int nt = 0; nt < 4; nt++) {
                int col = n0 + nwo + nt * 8 + tig * 2;
                atomicAdd(&C[(long)row * N + col],           acc[mt][nt][0]);
                atomicAdd(&C[(long)row * N + col + 1],       acc[mt][nt][1]);
                atomicAdd(&C[(long)(row + 8) * N + col],     acc[mt][nt][2]);
                atomicAdd(&C[(long)(row + 8) * N + col + 1], acc[mt][nt][3]);
            }
        }
    }
}

// ---------------- GEMM2: ci @ [Whc;Wtc]^T with fused activation epilogue ----------------
__global__ __launch_bounds__(256) void k_gemm2(const int* __restrict__ hts)
{
    extern __shared__ __align__(16) char smem[];
    const float* A = &g_buf[O_CI];
    const float* B = &g_buf[O_WTF];
    const int N = 1536, K = Dc;

    const uint32_t sb = smem_u32(smem);
    const int tid  = threadIdx.x;
    const int lane = tid & 31;
    const int wid  = tid >> 5;
    const int g    = lane >> 2;
    const int tig  = lane & 3;
    const int mwo  = (wid >> 2) * 64;
    const int nwo  = (wid & 3) * 32;
    const int m0   = blockIdx.y * 128;
    const int n0   = blockIdx.x * 128;

    const int crow = tid >> 1;
    const int cseg = (tid & 1) * 4;

    float acc[4][4][4];
    #pragma unroll
    for (int mt = 0; mt < 4; mt++)
        #pragma unroll
        for (int nt = 0; nt < 4; nt++)
            #pragma unroll
            for (int q = 0; q < 4; q++) acc[mt][nt][q] = 0.f;

    const int nch = K >> 5;

    auto issue = [&](int c) {
        int s = c & 1;
        int k0 = c << 5;
        uint32_t da = sb + s * (2 * TC_STAGE) + crow * TC_ROWB;
        const float* pa = A + (long)(m0 + crow) * K + k0;
        #pragma unroll
        for (int j = 0; j < 4; j++)
            asm volatile("cp.async.cg.shared.global [%0], [%1], 16;"
                         :: "r"(da + (cseg + j) * 16), "l"(pa + (cseg + j) * 4));
        uint32_t db = da + TC_STAGE;
        const float* pb = B + (long)(n0 + crow) * K + k0;
        #pragma unroll
        for (int j = 0; j < 4; j++)
            asm volatile("cp.async.cg.shared.global [%0], [%1], 16;"
                         :: "r"(db + (cseg + j) * 16), "l"(pb + (cseg + j) * 4));
        asm volatile("cp.async.commit_group;" ::: "memory");
    };

    issue(0);
    for (int c = 0; c < nch; c++) {
        if (c + 1 < nch) {
            issue(c + 1);
            asm volatile("cp.async.wait_group 1;" ::: "memory");
        } else {
            asm volatile("cp.async.wait_group 0;" ::: "memory");
        }
        __syncthreads();

        const uint32_t* Aw = reinterpret_cast<const uint32_t*>(smem + (c & 1) * 2 * TC_STAGE);
        const uint32_t* Bw = reinterpret_cast<const uint32_t*>(smem + (c & 1) * 2 * TC_STAGE + TC_STAGE);

        #pragma unroll
        for (int ks = 0; ks < 4; ks++) {
            const int kw = ks * 8 + tig;
            uint32_t af[4][4], bfr[4][2];
            #pragma unroll
            for (int mt = 0; mt < 4; mt++) {
                int r = mwo + mt * 16 + g;
                af[mt][0] = Aw[r * 36 + kw];
                af[mt][1] = Aw[(r + 8) * 36 + kw];
                af[mt][2] = Aw[r * 36 + kw + 4];
                af[mt][3] = Aw[(r + 8) * 36 + kw + 4];
            }
            #pragma unroll
            for (int nt = 0; nt < 4; nt++) {
                int cc = nwo + nt * 8 + g;
                bfr[nt][0] = Bw[cc * 36 + kw];
                bfr[nt][1] = Bw[cc * 36 + kw + 4];
            }
            #pragma unroll
            for (int mt = 0; mt < 4; mt++)
                #pragma unroll
                for (int nt = 0; nt < 4; nt++) {
                    asm volatile(
                        "mma.sync.aligned.m16n8k8.row.col.f32.tf32.tf32.f32 "
                        "{%0,%1,%2,%3}, {%4,%5,%6,%7}, {%8,%9}, {%0,%1,%2,%3};\n"
                        : "+f"(acc[mt][nt][0]), "+f"(acc[mt][nt][1]),
                          "+f"(acc[mt][nt][2]), "+f"(acc[mt][nt][3])
                        : "r"(af[mt][0]), "r"(af[mt][1]), "r"(af[mt][2]), "r"(af[mt][3]),
                          "r"(bfr[nt][0]), "r"(bfr[nt][1]));
                }
        }
        __syncthreads();
    }

    const bool isT = (n0 >= 768);
    const long dstBase = isT ? O_T2 : O_H2;
    const int  colOff  = isT ? 768 : 0;
    #pragma unroll
    for (int mt = 0; mt < 4; mt++) {
        #pragma unroll
        for (int half = 0; half < 2; half++) {
            int row = m0 + mwo + mt * 16 + g + half * 8;
            int b   = row >> 10;
            int hi  = hts[row * 2];
            int ti  = hts[row * 2 + 1];
            float maskf = (hi + ti) != 0 ? 1.f : 0.f;
            long erow = (long)(b * Ec + (isT ? ti : hi)) * 1536;
            #pragma unroll
            for (int nt = 0; nt < 4; nt++) {
                int col = n0 + nwo + nt * 8 + tig * 2;
                float2 e  = *reinterpret_cast<const float2*>(&g_buf[O_EHHT + erow + col]);
                float2 bb = *reinterpret_cast<const float2*>(&g_buf[O_BIAS + col]);
                float v0 = tanhf(acc[mt][nt][half * 2 + 0] + maskf * e.x + bb.x);
                float v1 = tanhf(acc[mt][nt][half * 2 + 1] + maskf * e.y + bb.y);
                *reinterpret_cast<float2*>(
                    &g_buf[dstBase + (long)row * Dc + col - colOff]) = make_float2(v0, v1);
            }
        }
    }
}

// ---------------- K9 fused (R9 form): bin_res += h2-tile · (t2-tile @ Wb^T) ----------------
__global__ __launch_bounds__(256) void k_binred(const float* __restrict__ Wbin,
                                                float* __restrict__ out)
{
    int mt = blockIdx.x;
    int n  = blockIdx.y;
    int o  = blockIdx.z;
    __shared__ float sA[64][65];
    __shared__ float sW[64][65];
    int tid = threadIdx.x;

    #pragma unroll
    for (int q = 0; q < 4; q++) {
        int idx = tid + q * 256;
        int r   = idx >> 4;
        int c4  = idx & 15;
        float4 v = *reinterpret_cast<const float4*>(
            &g_buf[O_T2 + (long)(mt * 64 + r) * Dc + n * 64 + c4 * 4]);
        sA[r][c4 * 4 + 0] = v.x;
        sA[r][c4 * 4 + 1] = v.y;
        sA[r][c4 * 4 + 2] = v.z;
        sA[r][c4 * 4 + 3] = v.w;
        float4 w = *reinterpret_cast<const float4*>(
            &Wbin[(long)o * (Dc * BSc) + n * 4096 + r * 64 + c4 * 4]);
        sW[c4 * 4 + 0][r] = w.x;
        sW[c4 * 4 + 1][r] = w.y;
        sW[c4 * 4 + 2][r] = w.z;
        sW[c4 * 4 + 3][r] = w.w;
    }
    __syncthreads();

    int tx = tid & 15, ty = tid >> 4;
    float acc[4][4];
    #pragma unroll
    for (int i = 0; i < 4; i++)
        #pragma unroll
        for (int j = 0; j < 4; j++) acc[i][j] = 0.f;

    #pragma unroll 8
    for (int k = 0; k < 64; k++) {
        float ar[4], br[4];
        #pragma unroll
        for (int r = 0; r < 4; r++) ar[r] = sA[ty * 4 + r][k];
        #pragma unroll
        for (int c = 0; c < 4; c++) br[c] = sW[k][tx * 4 + c];
        #pragma unroll
        for (int r = 0; r < 4; r++)
            #pragma unroll
            for (int c = 0; c < 4; c++)
                acc[r][c] = fmaf(ar[r], br[c], acc[r][c]);
    }

    float part[4];
    #pragma unroll
    for (int r = 0; r < 4; r++) {
        float4 h = *reinterpret_cast<const float4*>(
            &g_buf[O_H2 + (long)(mt * 64 + ty * 4 + r) * Dc + n * 64 + tx * 4]);
        float p;
        p = fmaf(acc[r][0], h.x, 0.f);
        p = fmaf(acc[r][1], h.y, p);
        p = fmaf(acc[r][2], h.z, p);
        p = fmaf(acc[r][3], h.w, p);
        part[r] = p;
    }
    #pragma unroll
    for (int m = 8; m > 0; m >>= 1) {
        #pragma unroll
        for (int r = 0; r < 4; r++)
            part[r] += __shfl_xor_sync(0xffffffffu, part[r], m);
    }
    if (tx == 0) {
        #pragma unroll
        for (int r = 0; r < 4; r++)
            atomicAdd(&out[(mt * 64 + ty * 4 + r) * 2 + o], part[r]);
    }
}

// ---------------- host launch ----------------
extern "C" void kernel_launch(void* const* d_in, const int* in_sizes, int n_in,
                              void* d_out, int out_size)
{
    const float* ctx  = (const float*)d_in[0];
    const float* att  = (const float*)d_in[1];
    const float* mm   = (const float*)d_in[2];
    const float* em   = (const float*)d_in[3];
    const int*   hts  = (const int*)d_in[4];
    const float* Wh   = (const float*)d_in[5];
    const float* bh   = (const float*)d_in[6];
    const float* Whc  = (const float*)d_in[7];
    const float* bhc  = (const float*)d_in[8];
    const float* Wt   = (const float*)d_in[9];
    const float* bt   = (const float*)d_in[10];
    const float* Wtc  = (const float*)d_in[11];
    const float* btc  = (const float*)d_in[12];
    const float* Wbin = (const float*)d_in[13];
    const float* bbin = (const float*)d_in[14];
    float* out = (float*)d_out;

    cudaFuncSetAttribute(k_gemm13, cudaFuncAttributeMaxDynamicSharedMemorySize, TC_SMEM);
    cudaFuncSetAttribute(k_gemm2,  cudaFuncAttributeMaxDynamicSharedMemorySize, TC_SMEM);

    // stage 1: fused independent prep (entity | emnorm | w2tf | ctxT)
    k_prep1<<<P1_TOTAL, 256>>>(ctx, em, mm, Whc, Wtc, Wh, Wt);

    // stage 2: fused (ent2tf+bias+outinit | entatt | EHHT zero)
    k_prep2<<<P2_TOTAL, 256>>>(att, bh, bhc, bt, btc, bbin, out);

    // stage 2b: ctx_att (depends on entatt)
    k_ctxatt<<<Bc * Pc, 256>>>(hts);

    // stage 3a: fused GEMM1 (ctx_att@ctxT) + GEMM3 (entity split-K) — independent bodies
    k_gemm13<<<G13_TOTAL, 256, TC_SMEM>>>();

    // stage 3b: ci @ [Whc;Wtc]^T with fused activation epilogue -> H2 / T2
    k_gemm2<<<dim3(1536 / 128, (Bc * Pc) / 128, 1), 256, TC_SMEM>>>(hts);

    // stage 4: fused grouped bilinear (1536 blocks)
    k_binred<<<dim3((Bc * Pc) / 64, NBc, 2), 256>>>(Wbin, out);
}

// round 17
// speedup vs baseline: 1.2262x; 1.0003x over previous
#include <cuda_runtime.h>
#include <cuda_bf16.h>
#include <math.h>
#include <stdint.h>

// Problem constants
#define Bc 4
#define Lc 1024
#define Dc 768
#define Hc 12
#define Mc 96
#define Ec 48
#define Pc 1024
#define BSc 64
#define NBc 12

// ---------------- scratch (single device global, no allocation) ----------------
constexpr long SZ_ENTITY  = (long)Bc * Ec * Dc;
constexpr long SZ_ENTATT  = (long)Bc * Hc * Ec * Lc;
constexpr long SZ_CTXATT  = (long)Bc * Pc * Lc;
constexpr long SZ_CTXT    = (long)Bc * Dc * Lc;
constexpr long SZ_BPD     = (long)Bc * Pc * Dc;
constexpr long SZ_W       = (long)Dc * Dc;

constexpr long O_ENTITY  = 0;
constexpr long O_ENTATT  = O_ENTITY + SZ_ENTITY;
constexpr long O_CTXATT  = O_ENTATT + SZ_ENTATT;     // tf32-rounded fp32
constexpr long O_CTXT    = O_CTXATT + SZ_CTXATT;     // tf32-rounded fp32 [B][D][L]
constexpr long O_CI      = O_CTXT + SZ_CTXT;         // tf32-rounded fp32
constexpr long O_EHHT    = O_CI + SZ_BPD;            // [256][1536]: entity@[Wh;Wt]^T
constexpr long O_BIAS    = O_EHHT + 256 * 1536;      // [1536]: bh+bhc | bt+btc
constexpr long O_WTF     = O_BIAS + 1536;            // 4 weights tf32 [N][K]: Whc,Wtc,Wh,Wt
constexpr long O_ETF     = O_WTF + 4 * SZ_W;         // entity tf32 padded [256][D]
constexpr long O_H2      = O_ETF + 256 * Dc;
constexpr long O_T2      = O_H2 + SZ_BPD;
constexpr long O_TOTAL   = O_T2 + SZ_BPD;

__device__ __align__(16) float g_buf[O_TOTAL];
__device__ int   g_nz_idx[(long)Bc * Ec * Lc];
__device__ float g_nz_w[(long)Bc * Ec * Lc];
__device__ int   g_nz_cnt[Bc * Ec];

__device__ __forceinline__ float f2tf(float f)
{
    unsigned r;
    asm("cvt.rna.tf32.f32 %0, %1;" : "=r"(r) : "f"(f));
    return __uint_as_float(r);
}

// ---------------- shared-memory union for the fused prep1 kernel ----------------
struct SEnt  { int mc; int midx[Mc]; float mw[Mc]; int lc; int lidx[Lc]; float lw[Lc]; };
struct SNorm { int mc; int midx[Mc]; float mw[Mc]; float tok[Lc]; float red[256]; float inv; };
struct SCtxT { float t[32][33]; };

#define P1_ENTITY_END  192
#define P1_EMNORM_END  384
#define P1_W2TF_END    (384 + 2304)
#define P1_TOTAL       (2688 + 3072)

__device__ void body_entity(void* smem, int be,
                            const float* __restrict__ ctx, const float* __restrict__ em,
                            const float* __restrict__ mm)
{
    SEnt* s = reinterpret_cast<SEnt*>(smem);
    int b = be / Ec;

    if (threadIdx.x < 32) {
        int cnt = 0;
        for (int base = 0; base < Mc; base += 32) {
            int m = base + threadIdx.x;
            float w = em[(long)be * Mc + m];
            unsigned msk = __ballot_sync(0xffffffffu, w != 0.f);
            if (w != 0.f) {
                int pos = cnt + __popc(msk & ((1u << threadIdx.x) - 1u));
                s->midx[pos] = m;
                s->mw[pos]   = w;
            }
            cnt += __popc(msk);
        }
        if (threadIdx.x == 0) s->mc = cnt;
    }
    __syncthreads();
    int mc = s->mc;

    float eacc[3] = {0.f, 0.f, 0.f};
    for (int j = 0; j < mc; j++) {
        if (threadIdx.x < 32) {
            const float* mrow = mm + ((long)b * Mc + s->midx[j]) * Lc;
            int cnt = 0;
            for (int base = 0; base < Lc; base += 32) {
                int l = base + threadIdx.x;
                float w = mrow[l];
                unsigned msk = __ballot_sync(0xffffffffu, w != 0.f);
                if (w != 0.f) {
                    int pos = cnt + __popc(msk & ((1u << threadIdx.x) - 1u));
                    s->lidx[pos] = l;
                    s->lw[pos]   = w;
                }
                cnt += __popc(msk);
            }
            if (threadIdx.x == 0) s->lc = cnt;
        }
        __syncthreads();
        int lc = s->lc;
        float wj = s->mw[j];
        #pragma unroll
        for (int q = 0; q < 3; q++) {
            int d = threadIdx.x + q * 256;
            float a = 0.f;
            for (int i = 0; i < lc; i++)
                a += s->lw[i] * ctx[((long)b * Lc + s->lidx[i]) * Dc + d];
            eacc[q] += wj * expf(a);
        }
        __syncthreads();
    }
    #pragma unroll
    for (int q = 0; q < 3; q++) {
        int d = threadIdx.x + q * 256;
        g_buf[O_ENTITY + (long)be * Dc + d] = (mc == 0) ? 0.f : logf(eacc[q]);
    }
}

__device__ void body_emnorm(void* smem, int be,
                            const float* __restrict__ em, const float* __restrict__ mm)
{
    SNorm* s = reinterpret_cast<SNorm*>(smem);
    int b = be / Ec;

    if (threadIdx.x < 32) {
        int cnt = 0;
        for (int base = 0; base < Mc; base += 32) {
            int m = base + threadIdx.x;
            float w = em[(long)be * Mc + m];
            unsigned msk = __ballot_sync(0xffffffffu, w != 0.f);
            if (w != 0.f) {
                int pos = cnt + __popc(msk & ((1u << threadIdx.x) - 1u));
                s->midx[pos] = m;
                s->mw[pos]   = w;
            }
            cnt += __popc(msk);
        }
        if (threadIdx.x == 0) s->mc = cnt;
    }
    __syncthreads();
    int mc = s->mc;

    float part = 0.f;
    for (int l = threadIdx.x; l < Lc; l += 256) {
        float a = 0.f;
        for (int j = 0; j < mc; j++)
            a += s->mw[j] * mm[((long)b * Mc + s->midx[j]) * Lc + l];
        s->tok[l] = a;
        part += a;
    }
    s->red[threadIdx.x] = part;
    __syncthreads();
    for (int st = 128; st > 0; st >>= 1) {
        if (threadIdx.x < st) s->red[threadIdx.x] += s->red[threadIdx.x + st];
        __syncthreads();
    }
    if (threadIdx.x == 0) s->inv = 1.f / (s->red[0] + 1e-20f);
    __syncthreads();
    float inv = s->inv;

    if (threadIdx.x < 32) {
        int cnt = 0;
        for (int base = 0; base < Lc; base += 32) {
            int l = base + threadIdx.x;
            float v = s->tok[l];
            unsigned msk = __ballot_sync(0xffffffffu, v != 0.f);
            if (v != 0.f) {
                int pos = cnt + __popc(msk & ((1u << threadIdx.x) - 1u));
                g_nz_idx[(long)be * Lc + pos] = l;
                g_nz_w[(long)be * Lc + pos]   = v * inv;
            }
            cnt += __popc(msk);
        }
        if (threadIdx.x == 0) g_nz_cnt[be] = cnt;
    }
}

__device__ void body_w2tf(int blk, const float* __restrict__ W0, const float* __restrict__ W1,
                          const float* __restrict__ W2, const float* __restrict__ W3)
{
    int wsel = blk / 576;
    int bx   = blk % 576;
    const float* W = (wsel == 0) ? W0 : (wsel == 1) ? W1 : (wsel == 2) ? W2 : W3;
    float* D = &g_buf[O_WTF + (long)wsel * SZ_W];
    long i = ((long)bx * 256 + threadIdx.x) * 4;
    float4 v = *reinterpret_cast<const float4*>(&W[i]);
    v.x = f2tf(v.x); v.y = f2tf(v.y); v.z = f2tf(v.z); v.w = f2tf(v.w);
    *reinterpret_cast<float4*>(&D[i]) = v;
}

__device__ void body_ctxT(void* smem, int blk, const float* __restrict__ ctx)
{
    SCtxT* s = reinterpret_cast<SCtxT*>(smem);
    int bx = blk % 24;
    int by = (blk / 24) % 32;
    int b  = blk / (24 * 32);
    int tx = threadIdx.x & 31;
    int ty = threadIdx.x >> 5;
    const float* W = ctx + (long)b * Lc * Dc;
    float* O = &g_buf[O_CTXT + (long)b * Dc * Lc];
    int x  = bx * 32 + tx;
    int y0 = by * 32;
    for (int i = ty; i < 32; i += 8)
        s->t[i][tx] = W[(long)(y0 + i) * Dc + x];
    __syncthreads();
    int x2 = by * 32 + tx;
    for (int i = ty; i < 32; i += 8)
        O[(long)(bx * 32 + i) * Lc + x2] = f2tf(s->t[tx][i]);
}

__global__ __launch_bounds__(256) void k_prep1(
    const float* __restrict__ ctx, const float* __restrict__ em, const float* __restrict__ mm,
    const float* __restrict__ W0, const float* __restrict__ W1,
    const float* __restrict__ W2, const float* __restrict__ W3)
{
    __shared__ __align__(16) char pool[sizeof(SEnt)];
    int blk = blockIdx.x;
    if (blk < P1_ENTITY_END) {
        body_entity(pool, blk, ctx, em, mm);
    } else if (blk < P1_EMNORM_END) {
        body_emnorm(pool, blk - P1_ENTITY_END, em, mm);
    } else if (blk < P1_W2TF_END) {
        body_w2tf(blk - P1_EMNORM_END, W0, W1, W2, W3);
    } else {
        body_ctxT(pool, blk - P1_W2TF_END, ctx);
    }
}

// ---------------- prep2: ent2tf+bias+outinit | entatt | EHHT zero (independent) ----------------
#define P2_ENT2TF_END 192
#define P2_ENTATT_END (192 + 2304)
#define P2_TOTAL      (192 + 2304 + 384)

__device__ void body_ent2tf(int blk,
                            const float* __restrict__ bh, const float* __restrict__ bhc,
                            const float* __restrict__ bt, const float* __restrict__ btc,
                            const float* __restrict__ bbin, float* __restrict__ out)
{
    long i = ((long)blk * 256 + threadIdx.x) * 4;
    int row = (int)(i / Dc);
    float4 v = make_float4(0.f, 0.f, 0.f, 0.f);
    if (row < Bc * Ec) {
        v = *reinterpret_cast<const float4*>(&g_buf[O_ENTITY + i]);
        v.x = f2tf(v.x); v.y = f2tf(v.y); v.z = f2tf(v.z); v.w = f2tf(v.w);
    }
    *reinterpret_cast<float4*>(&g_buf[O_ETF + i]) = v;
    int t = blk * 256 + threadIdx.x;
    if (t < 768)        g_buf[O_BIAS + t] = bh[t] + bhc[t];
    else if (t < 1536)  g_buf[O_BIAS + t] = bt[t - 768] + btc[t - 768];
    if (t < Bc * Pc * 2) out[t] = bbin[t & 1];
}

__device__ void body_entatt(int id, const float* __restrict__ att)
{
    int e  = id % Ec;
    int bh = id / Ec;
    int b  = bh / Hc;
    int be = b * Ec + e;
    int cnt = g_nz_cnt[be];
    int tid = threadIdx.x;

    float4 acc = make_float4(0.f, 0.f, 0.f, 0.f);
    for (int j = 0; j < cnt; j++) {
        int   l = g_nz_idx[(long)be * Lc + j];
        float w = g_nz_w[(long)be * Lc + j];
        float4 rv = reinterpret_cast<const float4*>(att + ((long)bh * Lc + l) * Lc)[tid];
        acc.x += w * rv.x;
        acc.y += w * rv.y;
        acc.z += w * rv.z;
        acc.w += w * rv.w;
    }
    reinterpret_cast<float4*>(&g_buf[O_ENTATT + (long)id * Lc])[tid] = acc;
}

__global__ __launch_bounds__(256) void k_prep2(
    const float* __restrict__ att,
    const float* __restrict__ bh, const float* __restrict__ bhc,
    const float* __restrict__ bt, const float* __restrict__ btc,
    const float* __restrict__ bbin, float* __restrict__ out)
{
    int blk = blockIdx.x;
    if (blk < P2_ENT2TF_END) {
        body_ent2tf(blk, bh, bhc, bt, btc, bbin, out);
    } else if (blk < P2_ENTATT_END) {
        body_entatt(blk - P2_ENT2TF_END, att);
    } else {
        long i = ((long)(blk - P2_ENTATT_END) * 256 + threadIdx.x) * 4;
        *reinterpret_cast<float4*>(&g_buf[O_EHHT + i]) = make_float4(0.f, 0.f, 0.f, 0.f);
    }
}

// ---------------- K5: ctx_att (normalized, pre-masked) -> tf32, float4 ----------------
__global__ void k_ctxatt(const int* __restrict__ hts)
{
    int bp = blockIdx.x;
    int b  = bp / Pc;
    int hi = hts[bp * 2];
    int ti = hts[bp * 2 + 1];
    float maskf = (hi + ti) != 0 ? 1.f : 0.f;
    int tid = threadIdx.x;

    const float4* ph = reinterpret_cast<const float4*>(
        &g_buf[O_ENTATT + ((long)b * Hc * Ec + hi) * Lc]);
    const float4* pt = reinterpret_cast<const float4*>(
        &g_buf[O_ENTATT + ((long)b * Hc * Ec + ti) * Lc]);
    const long step4 = (long)Ec * Lc / 4;

    float4 v = make_float4(0.f, 0.f, 0.f, 0.f);
    #pragma unroll
    for (int h = 0; h < Hc; h++) {
        float4 a = ph[h * step4 + tid];
        float4 c = pt[h * step4 + tid];
        v.x += a.x * c.x;
        v.y += a.y * c.y;
        v.z += a.z * c.z;
        v.w += a.w * c.w;
    }
    float part = (v.x + v.y) + (v.z + v.w);

    __shared__ float s_red[256];
    __shared__ float s_inv;
    s_red[tid] = part;
    __syncthreads();
    for (int s = 128; s > 0; s >>= 1) {
        if (tid < s) s_red[tid] += s_red[tid + s];
        __syncthreads();
    }
    if (tid == 0) s_inv = maskf / (s_red[0] + 1e-20f);
    __syncthreads();
    float inv = s_inv;
    float4 o;
    o.x = f2tf(v.x * inv);
    o.y = f2tf(v.y * inv);
    o.z = f2tf(v.z * inv);
    o.w = f2tf(v.w * inv);
    reinterpret_cast<float4*>(&g_buf[O_CTXATT + (long)bp * Lc])[tid] = o;
}

// ================= tf32 mma.sync GEMM infrastructure =================
__device__ __forceinline__ uint32_t smem_u32(const void* p)
{
    uint32_t a;
    asm("{ .reg .u64 t; cvta.to.shared.u64 t, %1; cvt.u32.u64 %0, t; }" : "=r"(a) : "l"(p));
    return a;
}

#define TC_ROWB   144
#define TC_STAGE  (128 * TC_ROWB)          // per-operand per-stage (18432 B)
#define TC_SSTRIDE (2 * TC_STAGE)          // A+B per stage (36864 B)
#define TC_NSTAGE 3
#define TC_SMEM   (TC_NSTAGE * TC_SSTRIDE) // 110592 B
#define SPLITK    8

// ---------------- fused GEMM1 (MODE1) + GEMM3 (split-K MODE3) in one launch -----------
#define G13_SPLIT 192
#define G13_TOTAL 384

__global__ __launch_bounds__(256) void k_gemm13()
{
    extern __shared__ __align__(16) char smem[];
    const int blk = blockIdx.x;

    const float* A;
    const float* B;
    float* C;
    int N, K, nch, m0, n0;
    bool mode1;

    if (blk < G13_SPLIT) {
        int bx = blk % 6, by = (blk / 6) % 8, bz = blk / 48;
        A = &g_buf[O_CTXATT + (long)bz * Pc * Lc];
        B = &g_buf[O_CTXT + (long)bz * Dc * Lc];
        C = &g_buf[O_CI + (long)bz * Pc * Dc];
        N = Dc; K = Lc; nch = Lc >> 5;
        m0 = by * 128; n0 = bx * 128;
        mode1 = true;
    } else {
        int id = blk - G13_SPLIT;
        int bx = id % 12, by = (id / 12) % 2, bz = id / 24;
        int seg = Dc / SPLITK;
        A = &g_buf[O_ETF] + (long)bz * seg;
        B = &g_buf[O_WTF + 2 * SZ_W] + (long)bz * seg;
        C = &g_buf[O_EHHT];
        N = 1536; K = Dc; nch = (Dc >> 5) / SPLITK;
        m0 = by * 128; n0 = bx * 128;
        mode1 = false;
    }

    const uint32_t sb = smem_u32(smem);
    const int tid  = threadIdx.x;
    const int lane = tid & 31;
    const int wid  = tid >> 5;
    const int g    = lane >> 2;
    const int tig  = lane & 3;
    const int mwo  = (wid >> 2) * 64;
    const int nwo  = (wid & 3) * 32;

    const int crow = tid >> 1;
    const int cseg = (tid & 1) * 4;

    float acc[4][4][4];
    #pragma unroll
    for (int mt = 0; mt < 4; mt++)
        #pragma unroll
        for (int nt = 0; nt < 4; nt++)
            #pragma unroll
            for (int q = 0; q < 4; q++) acc[mt][nt][q] = 0.f;

    // issue stage c (empty commit past nch to keep group accounting uniform)
    auto issue = [&](int c) {
        if (c < nch) {
            int s = c % TC_NSTAGE;
            int k0 = c << 5;
            uint32_t da = sb + s * TC_SSTRIDE + crow * TC_ROWB;
            const float* pa = A + (long)(m0 + crow) * K + k0;
            #pragma unroll
            for (int j = 0; j < 4; j++)
                asm volatile("cp.async.cg.shared.global [%0], [%1], 16;"
                             :: "r"(da + (cseg + j) * 16), "l"(pa + (cseg + j) * 4));
            uint32_t db = da + TC_STAGE;
            const float* pb = B + (long)(n0 + crow) * K + k0;
            #pragma unroll
            for (int j = 0; j < 4; j++)
                asm volatile("cp.async.cg.shared.global [%0], [%1], 16;"
                             :: "r"(db + (cseg + j) * 16), "l"(pb + (cseg + j) * 4));
        }
        asm volatile("cp.async.commit_group;" ::: "memory");
    };

    issue(0);
    issue(1);
    for (int c = 0; c < nch; c++) {
        asm volatile("cp.async.wait_group 1;" ::: "memory");
        __syncthreads();
        issue(c + 2);

        const uint32_t* Aw = reinterpret_cast<const uint32_t*>(smem + (c % TC_NSTAGE) * TC_SSTRIDE);
        const uint32_t* Bw = Aw + TC_STAGE / 4;

        #pragma unroll
        for (int ks = 0; ks < 4; ks++) {
            const int kw = ks * 8 + tig;
            uint32_t af[4][4], bfr[4][2];
            #pragma unroll
            for (int mt = 0; mt < 4; mt++) {
                int r = mwo + mt * 16 + g;
                af[mt][0] = Aw[r * 36 + kw];
                af[mt][1] = Aw[(r + 8) * 36 + kw];
                af[mt][2] = Aw[r * 36 + kw + 4];
                af[mt][3] = Aw[(r + 8) * 36 + kw + 4];
            }
            #pragma unroll
            for (int nt = 0; nt < 4; nt++) {
                int cc = nwo + nt * 8 + g;
                bfr[nt][0] = Bw[cc * 36 + kw];
                bfr[nt][1] = Bw[cc * 36 + kw + 4];
            }
            #pragma unroll
            for (int mt = 0; mt < 4; mt++)
                #pragma unroll
                for (int nt = 0; nt < 4; nt++) {
                    asm volatile(
                        "mma.sync.aligned.m16n8k8.row.col.f32.tf32.tf32.f32 "
                        "{%0,%1,%2,%3}, {%4,%5,%6,%7}, {%8,%9}, {%0,%1,%2,%3};\n"
                        : "+f"(acc[mt][nt][0]), "+f"(acc[mt][nt][1]),
                          "+f"(acc[mt][nt][2]), "+f"(acc[mt][nt][3])
                        : "r"(af[mt][0]), "r"(af[mt][1]), "r"(af[mt][2]), "r"(af[mt][3]),
                          "r"(bfr[nt][0]), "r"(bfr[nt][1]));
                }
        }
    }

    if (mode1) {
        #pragma unroll
        for (int mt = 0; mt < 4; mt++) {
            int row = m0 + mwo + mt * 16 + g;
            #pragma unroll
            for (int nt = 0; nt < 4; nt++) {
                int col = n0 + nwo + nt * 8 + tig * 2;
                float2 v0 = make_float2(f2tf(acc[mt][nt][0]), f2tf(acc[mt][nt][1]));
                float2 v1 = make_float2(f2tf(acc[mt][nt][2]), f2tf(acc[mt][nt][3]));
                *reinterpret_cast<float2*>(&C[(long)row * N + col])       = v0;
                *reinterpret_cast<float2*>(&C[(long)(row + 8) * N + col]) = v1;
            }
        }
    } else {
        #pragma unroll
        for (int mt = 0; mt < 4; mt++) {
            int row = m0 + mwo + mt * 16 + g;
            #pragma unroll
            for (int nt = 0; nt < 4; nt++) {
                int col = n0 + nwo + nt * 8 + tig * 2;
                atomicAdd(&C[(long)row * N + col],           acc[mt][nt][0]);
                atomicAdd(&C[(long)row * N + col + 1],       acc[mt][nt][1]);
                atomicAdd(&C[(long)(row + 8) * N + col],     acc[mt][nt][2]);
                atomicAdd(&C[(long)(row + 8) * N + col + 1], acc[mt][nt][3]);
            }
        }
    }
}

// ---------------- GEMM2: ci @ [Whc;Wtc]^T with fused activation epilogue ----------------
__global__ __launch_bounds__(256) void k_gemm2(const int* __restrict__ hts)
{
    extern __shared__ __align__(16) char smem[];
    const float* A = &g_buf[O_CI];
    const float* B = &g_buf[O_WTF];
    const int N = 1536, K = Dc;

    const uint32_t sb = smem_u32(smem);
    const int tid  = threadIdx.x;
    const int lane = tid & 31;
    const int wid  = tid >> 5;
    const int g    = lane >> 2;
    const int tig  = lane & 3;
    const int mwo  = (wid >> 2) * 64;
    const int nwo  = (wid & 3) * 32;
    const int m0   = blockIdx.y * 128;
    const int n0   = blockIdx.x * 128;

    const int crow = tid >> 1;
    const int cseg = (tid & 1) * 4;

    float acc[4][4][4];
    #pragma unroll
    for (int mt = 0; mt < 4; mt++)
        #pragma unroll
        for (int nt = 0; nt < 4; nt++)
            #pragma unroll
            for (int q = 0; q < 4; q++) acc[mt][nt][q] = 0.f;

    const int nch = K >> 5;

    auto issue = [&](int c) {
        if (c < nch) {
            int s = c % TC_NSTAGE;
            int k0 = c << 5;
            uint32_t da = sb + s * TC_SSTRIDE + crow * TC_ROWB;
            const float* pa = A + (long)(m0 + crow) * K + k0;
            #pragma unroll
            for (int j = 0; j < 4; j++)
                asm volatile("cp.async.cg.shared.global [%0], [%1], 16;"
                             :: "r"(da + (cseg + j) * 16), "l"(pa + (cseg + j) * 4));
            uint32_t db = da + TC_STAGE;
            const float* pb = B + (long)(n0 + crow) * K + k0;
            #pragma unroll
            for (int j = 0; j < 4; j++)
                asm volatile("cp.async.cg.shared.global [%0], [%1], 16;"
                             :: "r"(db + (cseg + j) * 16), "l"(pb + (cseg + j) * 4));
        }
        asm volatile("cp.async.commit_group;" ::: "memory");
    };

    issue(0);
    issue(1);
    for (int c = 0; c < nch; c++) {
        asm volatile("cp.async.wait_group 1;" ::: "memory");
        __syncthreads();
        issue(c + 2);

        const uint32_t* Aw = reinterpret_cast<const uint32_t*>(smem + (c % TC_NSTAGE) * TC_SSTRIDE);
        const uint32_t* Bw = Aw + TC_STAGE / 4;

        #pragma unroll
        for (int ks = 0; ks < 4; ks++) {
            const int kw = ks * 8 + tig;
            uint32_t af[4][4], bfr[4][2];
            #pragma unroll
            for (int mt = 0; mt < 4; mt++) {
                int r = mwo + mt * 16 + g;
                af[mt][0] = Aw[r * 36 + kw];
                af[mt][1] = Aw[(r + 8) * 36 + kw];
                af[mt][2] = Aw[r * 36 + kw + 4];
                af[mt][3] = Aw[(r + 8) * 36 + kw + 4];
            }
            #pragma unroll
            for (int nt = 0; nt < 4; nt++) {
                int cc = nwo + nt * 8 + g;
                bfr[nt][0] = Bw[cc * 36 + kw];
                bfr[nt][1] = Bw[cc * 36 + kw + 4];
            }
            #pragma unroll
            for (int mt = 0; mt < 4; mt++)
                #pragma unroll
                for (int nt = 0; nt < 4; nt++) {
                    asm volatile(
                        "mma.sync.aligned.m16n8k8.row.col.f32.tf32.tf32.f32 "
                        "{%0,%1,%2,%3}, {%4,%5,%6,%7}, {%8,%9}, {%0,%1,%2,%3};\n"
                        : "+f"(acc[mt][nt][0]), "+f"(acc[mt][nt][1]),
                          "+f"(acc[mt][nt][2]), "+f"(acc[mt][nt][3])
                        : "r"(af[mt][0]), "r"(af[mt][1]), "r"(af[mt][2]), "r"(af[mt][3]),
                          "r"(bfr[nt][0]), "r"(bfr[nt][1]));
                }
        }
    }

    const bool isT = (n0 >= 768);
    const long dstBase = isT ? O_T2 : O_H2;
    const int  colOff  = isT ? 768 : 0;
    #pragma unroll
    for (int mt = 0; mt < 4; mt++) {
        #pragma unroll
        for (int half = 0; half < 2; half++) {
            int row = m0 + mwo + mt * 16 + g + half * 8;
            int b   = row >> 10;
            int hi  = hts[row * 2];
            int ti  = hts[row * 2 + 1];
            float maskf = (hi + ti) != 0 ? 1.f : 0.f;
            long erow = (long)(b * Ec + (isT ? ti : hi)) * 1536;
            #pragma unroll
            for (int nt = 0; nt < 4; nt++) {
                int col = n0 + nwo + nt * 8 + tig * 2;
                float2 e  = *reinterpret_cast<const float2*>(&g_buf[O_EHHT + erow + col]);
                float2 bb = *reinterpret_cast<const float2*>(&g_buf[O_BIAS + col]);
                float v0 = tanhf(acc[mt][nt][half * 2 + 0] + maskf * e.x + bb.x);
                float v1 = tanhf(acc[mt][nt][half * 2 + 1] + maskf * e.y + bb.y);
                *reinterpret_cast<float2*>(
                    &g_buf[dstBase + (long)row * Dc + col - colOff]) = make_float2(v0, v1);
            }
        }
    }
}

// ---------------- K9 fused (R9 form): bin_res += h2-tile · (t2-tile @ Wb^T) ----------------
__global__ __launch_bounds__(256) void k_binred(const float* __restrict__ Wbin,
                                                float* __restrict__ out)
{
    int mt = blockIdx.x;
    int n  = blockIdx.y;
    int o  = blockIdx.z;
    __shared__ float sA[64][65];
    __shared__ float sW[64][65];
    int tid = threadIdx.x;

    #pragma unroll
    for (int q = 0; q < 4; q++) {
        int idx = tid + q * 256;
        int r   = idx >> 4;
        int c4  = idx & 15;
        float4 v = *reinterpret_cast<const float4*>(
            &g_buf[O_T2 + (long)(mt * 64 + r) * Dc + n * 64 + c4 * 4]);
        sA[r][c4 * 4 + 0] = v.x;
        sA[r][c4 * 4 + 1] = v.y;
        sA[r][c4 * 4 + 2] = v.z;
        sA[r][c4 * 4 + 3] = v.w;
        float4 w = *reinterpret_cast<const float4*>(
            &Wbin[(long)o * (Dc * BSc) + n * 4096 + r * 64 + c4 * 4]);
        sW[c4 * 4 + 0][r] = w.x;
        sW[c4 * 4 + 1][r] = w.y;
        sW[c4 * 4 + 2][r] = w.z;
        sW[c4 * 4 + 3][r] = w.w;
    }
    __syncthreads();

    int tx = tid & 15, ty = tid >> 4;
    float acc[4][4];
    #pragma unroll
    for (int i = 0; i < 4; i++)
        #pragma unroll
        for (int j = 0; j < 4; j++) acc[i][j] = 0.f;

    #pragma unroll 8
    for (int k = 0; k < 64; k++) {
        float ar[4], br[4];
        #pragma unroll
        for (int r = 0; r < 4; r++) ar[r] = sA[ty * 4 + r][k];
        #pragma unroll
        for (int c = 0; c < 4; c++) br[c] = sW[k][tx * 4 + c];
        #pragma unroll
        for (int r = 0; r < 4; r++)
            #pragma unroll
            for (int c = 0; c < 4; c++)
                acc[r][c] = fmaf(ar[r], br[c], acc[r][c]);
    }

    float part[4];
    #pragma unroll
    for (int r = 0; r < 4; r++) {
        float4 h = *reinterpret_cast<const float4*>(
            &g_buf[O_H2 + (long)(mt * 64 + ty * 4 + r) * Dc + n * 64 + tx * 4]);
        float p;
        p = fmaf(acc[r][0], h.x, 0.f);
        p = fmaf(acc[r][1], h.y, p);
        p = fmaf(acc[r][2], h.z, p);
        p = fmaf(acc[r][3], h.w, p);
        part[r] = p;
    }
    #pragma unroll
    for (int m = 8; m > 0; m >>= 1) {
        #pragma unroll
        for (int r = 0; r < 4; r++)
            part[r] += __shfl_xor_sync(0xffffffffu, part[r], m);
    }
    if (tx == 0) {
        #pragma unroll
        for (int r = 0; r < 4; r++)
            atomicAdd(&out[(mt * 64 + ty * 4 + r) * 2 + o], part[r]);
    }
}

// ---------------- host launch ----------------
extern "C" void kernel_launch(void* const* d_in, const int* in_sizes, int n_in,
                              void* d_out, int out_size)
{
    const float* ctx  = (const float*)d_in[0];
    const float* att  = (const float*)d_in[1];
    const float* mm   = (const float*)d_in[2];
    const float* em   = (const float*)d_in[3];
    const int*   hts  = (const int*)d_in[4];
    const float* Wh   = (const float*)d_in[5];
    const float* bh   = (const float*)d_in[6];
    const float* Whc  = (const float*)d_in[7];
    const float* bhc  = (const float*)d_in[8];
    const float* Wt   = (const float*)d_in[9];
    const float* bt   = (const float*)d_in[10];
    const float* Wtc  = (const float*)d_in[11];
    const float* btc  = (const float*)d_in[12];
    const float* Wbin = (const float*)d_in[13];
    const float* bbin = (const float*)d_in[14];
    float* out = (float*)d_out;

    cudaFuncSetAttribute(k_gemm13, cudaFuncAttributeMaxDynamicSharedMemorySize, TC_SMEM);
    cudaFuncSetAttribute(k_gemm2,  cudaFuncAttributeMaxDynamicSharedMemorySize, TC_SMEM);

    // stage 1: fused independent prep (entity | emnorm | w2tf | ctxT)
    k_prep1<<<P1_TOTAL, 256>>>(ctx, em, mm, Whc, Wtc, Wh, Wt);

    // stage 2: fused (ent2tf+bias+outinit | entatt | EHHT zero)
    k_prep2<<<P2_TOTAL, 256>>>(att, bh, bhc, bt, btc, bbin, out);

    // stage 2b: ctx_att (depends on entatt)
    k_ctxatt<<<Bc * Pc, 256>>>(hts);

    // stage 3a: fused GEMM1 (ctx_att@ctxT) + GEMM3 (entity split-K) — 3-stage pipeline
    k_gemm13<<<G13_TOTAL, 256, TC_SMEM>>>();

    // stage 3b: ci @ [Whc;Wtc]^T with fused activation epilogue -> H2 / T2
    k_gemm2<<<dim3(1536 / 128, (Bc * Pc) / 128, 1), 256, TC_SMEM>>>(hts);

    // stage 4: fused grouped bilinear (1536 blocks)
    k_binred<<<dim3((Bc * Pc) / 64, NBc, 2), 256>>>(Wbin, out);
}